// round 3
// baseline (speedup 1.0000x reference)
#include <cuda_runtime.h>
#include <math.h>

#define BB 32
#define NN 4096
#define FF 768
#define DD 256
#define KS 8
#define HKV 512
#define NROWS (BB*NN)
#define SROWS (BB*KS)
#define EPSN 1e-8f
#define QSCALE 0.0625f

/* ------------------ device scratch (static, no allocs) ------------------ */
static __device__ float d_kv[(size_t)NROWS*HKV];   /* k|v per row, 268MB */
static __device__ float d_wp[FF*HKV];
static __device__ float d_c1[HKV];
static __device__ float d_c0[HKV];
static __device__ float d_wqT[DD*DD];
static __device__ float d_wihT[DD*3*DD];
static __device__ float d_whhT[DD*3*DD];
static __device__ float d_w1T[DD*DD];
static __device__ float d_w2T[DD*DD];
static __device__ float d_q[SROWS*DD];
static __device__ float d_attn[(size_t)SROWS*NN];
static __device__ float d_rowsum[SROWS];
static __device__ float d_updates[SROWS*DD];
static __device__ float d_h[SROWS*DD];
static __device__ float d_slots[SROWS*DD];

__device__ __forceinline__ float sigf(float x) { return 1.f / (1.f + __expf(-x)); }

/* ------------------------------ prep ------------------------------ */
__global__ void copy_slots(const float* __restrict__ prev) {
    int i = blockIdx.x * blockDim.x + threadIdx.x;
    d_slots[i] = prev[i];
}

__global__ void prep_wp(const float* __restrict__ Wk, const float* __restrict__ Wv,
                        const float* __restrict__ g_in) {
    int f = blockIdx.x, h = threadIdx.x;
    float w = (h < DD) ? Wk[h*FF + f] : Wv[(h-DD)*FF + f];
    d_wp[f*HKV + h] = g_in[f] * w;
}

__global__ void prep_c(const float* __restrict__ Wk, const float* __restrict__ Wv,
                       const float* __restrict__ b_in) {
    int h = threadIdx.x;
    float s1 = 0.f, s0 = 0.f;
    for (int f = 0; f < FF; f++) {
        s1 += d_wp[f*HKV + h];
        float w = (h < DD) ? Wk[h*FF + f] : Wv[(h-DD)*FF + f];
        s0 += b_in[f] * w;
    }
    d_c1[h] = s1; d_c0[h] = s0;
}

__global__ void transpose_sel(const float* __restrict__ src, int R, int C, int which) {
    float* dst = (which == 0) ? d_wqT : (which == 1) ? d_wihT :
                 (which == 2) ? d_whhT : (which == 3) ? d_w1T : d_w2T;
    int idx = blockIdx.x * blockDim.x + threadIdx.x;
    if (idx < R * C) {
        int r = idx / C, c = idx - r * C;
        dst[c * R + r] = src[idx];
    }
}

/* ---------------- fused LN + KV GEMM: 131072 x 512, K=768 ----------------
 * C[r][h] = rs*( (X@Wp)[r][h] - m*c1[h] ) + c0[h]
 * BM=128 BN=128 BK=16, 256 threads, 8x8 microtile. */
__launch_bounds__(256)
__global__ void gemm_kv(const float* __restrict__ X) {
    __shared__ float As[16][128];
    __shared__ float Bs[16][128];
    __shared__ float m_s[128], r_s[128], c1s[128], c0s[128];

    int tid = threadIdx.x;
    int c0b = blockIdx.x * 128;
    int r0  = blockIdx.y * 128;
    int tx = tid & 15, ty = tid >> 4;          /* cols tx*8, rows ty*8 */
    int arow = tid >> 2, ac4 = tid & 3;        /* A loads: rows arow, arow+64 */
    int brow = tid >> 5, bc4 = tid & 31;       /* B loads: rows brow, brow+8 */

    if (tid < 128) { c1s[tid] = d_c1[c0b + tid]; c0s[tid] = d_c0[c0b + tid]; }

    float acc[8][8];
#pragma unroll
    for (int i = 0; i < 8; i++)
#pragma unroll
        for (int j = 0; j < 8; j++) acc[i][j] = 0.f;

    float ps0 = 0.f, pq0 = 0.f, ps1 = 0.f, pq1 = 0.f;

    for (int k0 = 0; k0 < FF; k0 += 16) {
        __syncthreads();
        float4 a0 = *(const float4*)&X[(size_t)(r0 + arow)      * FF + k0 + ac4 * 4];
        float4 a1 = *(const float4*)&X[(size_t)(r0 + arow + 64) * FF + k0 + ac4 * 4];
        As[ac4*4+0][arow] = a0.x; As[ac4*4+1][arow] = a0.y;
        As[ac4*4+2][arow] = a0.z; As[ac4*4+3][arow] = a0.w;
        As[ac4*4+0][arow+64] = a1.x; As[ac4*4+1][arow+64] = a1.y;
        As[ac4*4+2][arow+64] = a1.z; As[ac4*4+3][arow+64] = a1.w;
        ps0 += a0.x + a0.y + a0.z + a0.w;
        pq0 += a0.x*a0.x + a0.y*a0.y + a0.z*a0.z + a0.w*a0.w;
        ps1 += a1.x + a1.y + a1.z + a1.w;
        pq1 += a1.x*a1.x + a1.y*a1.y + a1.z*a1.z + a1.w*a1.w;

        float4 b0 = *(const float4*)&d_wp[(k0 + brow)     * HKV + c0b + bc4 * 4];
        float4 b1 = *(const float4*)&d_wp[(k0 + brow + 8) * HKV + c0b + bc4 * 4];
        *(float4*)&Bs[brow][bc4*4]   = b0;
        *(float4*)&Bs[brow+8][bc4*4] = b1;
        __syncthreads();

#pragma unroll
        for (int kk = 0; kk < 16; kk++) {
            float a[8], b[8];
            *(float4*)&a[0] = *(const float4*)&As[kk][ty*8];
            *(float4*)&a[4] = *(const float4*)&As[kk][ty*8+4];
            *(float4*)&b[0] = *(const float4*)&Bs[kk][tx*8];
            *(float4*)&b[4] = *(const float4*)&Bs[kk][tx*8+4];
#pragma unroll
            for (int i = 0; i < 8; i++)
#pragma unroll
                for (int j = 0; j < 8; j++) acc[i][j] += a[i] * b[j];
        }
    }

    /* LN stats: reduce over the 4 lanes sharing each A row */
    ps0 += __shfl_xor_sync(0xffffffffu, ps0, 1); ps0 += __shfl_xor_sync(0xffffffffu, ps0, 2);
    pq0 += __shfl_xor_sync(0xffffffffu, pq0, 1); pq0 += __shfl_xor_sync(0xffffffffu, pq0, 2);
    ps1 += __shfl_xor_sync(0xffffffffu, ps1, 1); ps1 += __shfl_xor_sync(0xffffffffu, ps1, 2);
    pq1 += __shfl_xor_sync(0xffffffffu, pq1, 1); pq1 += __shfl_xor_sync(0xffffffffu, pq1, 2);
    if ((tid & 3) == 0) {
        float m0 = ps0 * (1.f/FF);
        m_s[arow] = m0;    r_s[arow]    = rsqrtf(pq0*(1.f/FF) - m0*m0 + 1e-5f);
        float m1 = ps1 * (1.f/FF);
        m_s[arow+64] = m1; r_s[arow+64] = rsqrtf(pq1*(1.f/FF) - m1*m1 + 1e-5f);
    }
    __syncthreads();

#pragma unroll
    for (int i = 0; i < 8; i++) {
        int r = ty * 8 + i;
        float m = m_s[r], rs = r_s[r];
        float out[8];
#pragma unroll
        for (int j = 0; j < 8; j++) {
            int c = tx * 8 + j;
            out[j] = rs * (acc[i][j] - m * c1s[c]) + c0s[c];
        }
        float* dst = &d_kv[(size_t)(r0 + r) * HKV + c0b + tx * 8];
        *(float4*)&dst[0] = *(float4*)&out[0];
        *(float4*)&dst[4] = *(float4*)&out[4];
    }
}

/* ---------------- slots LN + q projection (q *= SCALE) ---------------- */
__global__ void slots_q(const float* __restrict__ g_s, const float* __restrict__ b_s) {
    __shared__ float lnr[DD];
    __shared__ float ws[8], wq[8];
    int row = blockIdx.x, t = threadIdx.x;
    float x = d_slots[row * DD + t];
    float s = x, q2 = x * x;
#pragma unroll
    for (int o = 16; o; o >>= 1) {
        s  += __shfl_xor_sync(0xffffffffu, s, o);
        q2 += __shfl_xor_sync(0xffffffffu, q2, o);
    }
    if ((t & 31) == 0) { ws[t >> 5] = s; wq[t >> 5] = q2; }
    __syncthreads();
    float S = 0.f, Q = 0.f;
#pragma unroll
    for (int i = 0; i < 8; i++) { S += ws[i]; Q += wq[i]; }
    float m = S * (1.f/DD);
    float rst = rsqrtf(Q * (1.f/DD) - m * m + 1e-5f);
    lnr[t] = (x - m) * rst * g_s[t] + b_s[t];
    __syncthreads();
    float acc = 0.f;
#pragma unroll 8
    for (int d = 0; d < DD; d++) acc += lnr[d] * d_wqT[d * DD + t];
    d_q[row * DD + t] = acc * QSCALE;
}

__global__ void zero_urs() {
    int i = blockIdx.x * blockDim.x + threadIdx.x;
    if (i < SROWS) d_rowsum[i] = 0.f;
    d_updates[i] = 0.f;
}

/* -------- logits + softmax over K + rowsum; 128 thr, 512 n/block -------- */
__launch_bounds__(128)
__global__ void attn_kernel(float* __restrict__ attn_out) {
    __shared__ float qs[KS * DD];
    __shared__ float ks[16][516];
    int b = blockIdx.y;
    int n0 = blockIdx.x * 512;
    int tid = threadIdx.x;

    for (int i = tid; i < KS * DD; i += 128) qs[i] = d_q[b * KS * DD + i];

    float acc[KS][4];
#pragma unroll
    for (int s = 0; s < KS; s++)
#pragma unroll
        for (int j = 0; j < 4; j++) acc[s][j] = 0.f;

    for (int h0 = 0; h0 < DD; h0 += 16) {
        __syncthreads();
#pragma unroll
        for (int j = 0; j < 16; j++) {
            int id = tid + j * 128;
            int row = id >> 2, c4 = id & 3;
            float4 v = *(const float4*)&d_kv[(size_t)(b * NN + n0 + row) * HKV + h0 + c4 * 4];
            ks[c4*4+0][row] = v.x; ks[c4*4+1][row] = v.y;
            ks[c4*4+2][row] = v.z; ks[c4*4+3][row] = v.w;
        }
        __syncthreads();
#pragma unroll
        for (int hh = 0; hh < 16; hh++) {
            float4 kv = *(const float4*)&ks[hh][tid * 4];
#pragma unroll
            for (int s = 0; s < KS; s++) {
                float q = qs[s * DD + h0 + hh];
                acc[s][0] += q * kv.x; acc[s][1] += q * kv.y;
                acc[s][2] += q * kv.z; acc[s][3] += q * kv.w;
            }
        }
    }
    int nb = n0 + tid * 4;
    float rsum[KS];
#pragma unroll
    for (int s = 0; s < KS; s++) rsum[s] = 0.f;
#pragma unroll
    for (int j = 0; j < 4; j++) {
        float mx = acc[0][j];
#pragma unroll
        for (int s = 1; s < KS; s++) mx = fmaxf(mx, acc[s][j]);
        float den = 0.f;
#pragma unroll
        for (int s = 0; s < KS; s++) { acc[s][j] = __expf(acc[s][j] - mx); den += acc[s][j]; }
        float inv = 1.f / den;
#pragma unroll
        for (int s = 0; s < KS; s++) { acc[s][j] *= inv; rsum[s] += acc[s][j]; }
    }
#pragma unroll
    for (int s = 0; s < KS; s++) {
        float4 o = make_float4(acc[s][0], acc[s][1], acc[s][2], acc[s][3]);
        *(float4*)&attn_out[(size_t)(b * KS + s) * NN + nb] = o;
    }
#pragma unroll
    for (int s = 0; s < KS; s++) {
        float v = rsum[s];
#pragma unroll
        for (int o = 16; o; o >>= 1) v += __shfl_xor_sync(0xffffffffu, v, o);
        if ((tid & 31) == 0) atomicAdd(&d_rowsum[b * KS + s], v);
    }
}

/* ---------------- updates += attn @ v (unnormalized) ---------------- */
__launch_bounds__(256)
__global__ void updates_kernel(const float* __restrict__ attn_in) {
    __shared__ float vs[32][256];
    __shared__ float as[KS][32];
    int b = blockIdx.y;
    int n0 = blockIdx.x * 512;
    int tid = threadIdx.x;
    int s = tid >> 5, lane = tid & 31, d8 = lane * 8;
    float acc[8];
#pragma unroll
    for (int i = 0; i < 8; i++) acc[i] = 0.f;
    for (int n1 = 0; n1 < 512; n1 += 32) {
        __syncthreads();
#pragma unroll
        for (int j = 0; j < 8; j++) {
            int id = tid + j * 256;
            int row = id >> 6, c4 = id & 63;
            *(float4*)&vs[row][c4*4] =
                *(const float4*)&d_kv[(size_t)(b * NN + n0 + n1 + row) * HKV + DD + c4 * 4];
        }
        as[s][lane] = attn_in[(size_t)(b * KS + s) * NN + n0 + n1 + lane];
        __syncthreads();
#pragma unroll
        for (int j = 0; j < 32; j++) {
            float a = as[s][j];
            float4 v0 = *(const float4*)&vs[j][d8];
            float4 v1 = *(const float4*)&vs[j][d8 + 4];
            acc[0] += a * v0.x; acc[1] += a * v0.y; acc[2] += a * v0.z; acc[3] += a * v0.w;
            acc[4] += a * v1.x; acc[5] += a * v1.y; acc[6] += a * v1.z; acc[7] += a * v1.w;
        }
    }
#pragma unroll
    for (int i = 0; i < 8; i++)
        atomicAdd(&d_updates[(b * KS + s) * DD + d8 + i], acc[i]);
}

/* ---------------- GRU cell: one block per slot row ---------------- */
__global__ void gru_kernel(const float* __restrict__ b_ih, const float* __restrict__ b_hh) {
    __shared__ float us[DD], ss[DD];
    int row = blockIdx.x, t = threadIdx.x;
    float inv = 1.f / (d_rowsum[row] + EPSN);
    us[t] = d_updates[row * DD + t] * inv;
    ss[t] = d_slots[row * DD + t];
    __syncthreads();
    float gir = 0.f, giz = 0.f, gin = 0.f, ghr = 0.f, ghz = 0.f, ghn = 0.f;
#pragma unroll 4
    for (int d = 0; d < DD; d++) {
        float u = us[d], sv = ss[d];
        const float* wi = &d_wihT[d * (3*DD)];
        const float* wh = &d_whhT[d * (3*DD)];
        gir += u * wi[t];        ghr += sv * wh[t];
        giz += u * wi[t + DD];   ghz += sv * wh[t + DD];
        gin += u * wi[t + 2*DD]; ghn += sv * wh[t + 2*DD];
    }
    gir += b_ih[t];        ghr += b_hh[t];
    giz += b_ih[t + DD];   ghz += b_hh[t + DD];
    gin += b_ih[t + 2*DD]; ghn += b_hh[t + 2*DD];
    float r = sigf(gir + ghr);
    float z = sigf(giz + ghz);
    float n = tanhf(gin + r * ghn);
    d_h[row * DD + t] = (1.f - z) * n + z * ss[t];
}

/* ---------------- MLP (LN -> W1,relu -> W2) + residual ---------------- */
__global__ void mlp_kernel(const float* __restrict__ g_m, const float* __restrict__ b_m,
                           const float* __restrict__ b1, const float* __restrict__ b2) {
    __shared__ float lnh[DD], m1[DD];
    __shared__ float ws[8], wq[8];
    int row = blockIdx.x, t = threadIdx.x;
    float h = d_h[row * DD + t];
    float s = h, q2 = h * h;
#pragma unroll
    for (int o = 16; o; o >>= 1) {
        s  += __shfl_xor_sync(0xffffffffu, s, o);
        q2 += __shfl_xor_sync(0xffffffffu, q2, o);
    }
    if ((t & 31) == 0) { ws[t >> 5] = s; wq[t >> 5] = q2; }
    __syncthreads();
    float S = 0.f, Q = 0.f;
#pragma unroll
    for (int i = 0; i < 8; i++) { S += ws[i]; Q += wq[i]; }
    float m = S * (1.f/DD);
    float rst = rsqrtf(Q * (1.f/DD) - m * m + 1e-5f);
    lnh[t] = (h - m) * rst * g_m[t] + b_m[t];
    __syncthreads();
    float a1 = 0.f;
#pragma unroll 8
    for (int d = 0; d < DD; d++) a1 += lnh[d] * d_w1T[d * DD + t];
    m1[t] = fmaxf(a1 + b1[t], 0.f);
    __syncthreads();
    float a2 = 0.f;
#pragma unroll 8
    for (int d = 0; d < DD; d++) a2 += m1[d] * d_w2T[d * DD + t];
    d_slots[row * DD + t] = h + a2 + b2[t];
}

/* ---------------- final blend ---------------- */
__global__ void final_out(const float* __restrict__ prev, float* __restrict__ out) {
    int row = blockIdx.x, t = threadIdx.x;
    float mask = sigf(d_rowsum[row] * (1.f / NN));
    out[row * DD + t] = d_slots[row * DD + t] * mask + prev[row * DD + t] * (1.f - mask);
}

/* ------------------------------ launch ------------------------------ */
extern "C" void kernel_launch(void* const* d_in, const int* in_sizes, int n_in,
                              void* d_out, int out_size) {
    const float* features = (const float*)d_in[0];
    const float* prev     = (const float*)d_in[1];
    const float* g_in     = (const float*)d_in[2];
    const float* b_in     = (const float*)d_in[3];
    const float* g_s      = (const float*)d_in[4];
    const float* b_s      = (const float*)d_in[5];
    const float* g_m      = (const float*)d_in[6];
    const float* b_m      = (const float*)d_in[7];
    const float* Wq       = (const float*)d_in[8];
    const float* Wk       = (const float*)d_in[9];
    const float* Wv       = (const float*)d_in[10];
    const float* W_ih     = (const float*)d_in[11];
    const float* W_hh     = (const float*)d_in[12];
    const float* b_ih     = (const float*)d_in[13];
    const float* b_hh     = (const float*)d_in[14];
    const float* W1       = (const float*)d_in[15];
    const float* b1       = (const float*)d_in[16];
    const float* W2       = (const float*)d_in[17];
    const float* b2       = (const float*)d_in[18];
    float* out = (float*)d_out;

    float* attn_scratch = nullptr;
    cudaGetSymbolAddress((void**)&attn_scratch, d_attn);
    float* attn_final = (out_size >= SROWS*DD + SROWS*NN) ? out + SROWS*DD : attn_scratch;

    /* prep */
    copy_slots<<<SROWS*DD/256, 256>>>(prev);
    prep_wp<<<FF, HKV>>>(Wk, Wv, g_in);
    prep_c<<<1, HKV>>>(Wk, Wv, b_in);
    transpose_sel<<<(DD*DD+255)/256, 256>>>(Wq, DD, DD, 0);
    transpose_sel<<<(3*DD*DD+255)/256, 256>>>(W_ih, 3*DD, DD, 1);
    transpose_sel<<<(3*DD*DD+255)/256, 256>>>(W_hh, 3*DD, DD, 2);
    transpose_sel<<<(DD*DD+255)/256, 256>>>(W1, DD, DD, 3);
    transpose_sel<<<(DD*DD+255)/256, 256>>>(W2, DD, DD, 4);

    /* big fused LN + KV projection */
    {
        dim3 grid(HKV/128, NROWS/128);
        gemm_kv<<<grid, 256>>>(features);
    }

    /* 3 slot-attention iterations */
    for (int it = 0; it < 3; it++) {
        slots_q<<<SROWS, DD>>>(g_s, b_s);
        zero_urs<<<SROWS*DD/256, 256>>>();
        {
            dim3 g(NN/512, BB);
            attn_kernel<<<g, 128>>>(attn_scratch);
            updates_kernel<<<g, 256>>>(attn_scratch);
        }
        gru_kernel<<<SROWS, DD>>>(b_ih, b_hh);
        mlp_kernel<<<SROWS, DD>>>(g_m, b_m, b1, b2);
    }

    /* final attention + confidence blend */
    slots_q<<<SROWS, DD>>>(g_s, b_s);
    zero_urs<<<SROWS*DD/256, 256>>>();
    {
        dim3 g(NN/512, BB);
        attn_kernel<<<g, 128>>>(attn_final);
    }
    final_out<<<SROWS, DD>>>(prev, out);
}

// round 4
// speedup vs baseline: 1.0064x; 1.0064x over previous
#include <cuda_runtime.h>
#include <math.h>

#define BB 32
#define NN 4096
#define FF 768
#define DD 256
#define KS 8
#define HKV 512
#define NROWS (BB*NN)
#define SROWS (BB*KS)
#define EPSN 1e-8f
#define QSCALE 0.0625f

/* ------------------ device scratch (static, no allocs) ------------------ */
static __device__ float d_kv[(size_t)NROWS*HKV];   /* k|v per row, 268MB */
static __device__ float d_wp[FF*HKV];
static __device__ float d_c1[HKV];
static __device__ float d_c0[HKV];
static __device__ float d_wqT[DD*DD];
static __device__ float d_wihT[DD*3*DD];
static __device__ float d_whhT[DD*3*DD];
static __device__ float d_w1T[DD*DD];
static __device__ float d_w2T[DD*DD];
static __device__ float d_q[SROWS*DD];
static __device__ float d_attn[(size_t)SROWS*NN];
static __device__ float d_rowsum[SROWS];
static __device__ float d_updates[SROWS*DD];
static __device__ float d_h[SROWS*DD];
static __device__ float d_slots[SROWS*DD];

__device__ __forceinline__ float sigf(float x) { return 1.f / (1.f + __expf(-x)); }

/* packed f32x2 helpers (FFMA2 is PTX-only; ptxas never auto-fuses) */
__device__ __forceinline__ void fma2(unsigned long long &d, unsigned long long a,
                                     unsigned long long b) {
    asm("fma.rn.f32x2 %0, %1, %2, %0;" : "+l"(d) : "l"(a), "l"(b));
}
__device__ __forceinline__ unsigned long long dup2(float x) {
    unsigned long long r;
    asm("mov.b64 %0, {%1, %1};" : "=l"(r) : "f"(x));
    return r;
}
__device__ __forceinline__ float2 unpk(unsigned long long v) {
    float2 f;
    asm("mov.b64 {%0, %1}, %2;" : "=f"(f.x), "=f"(f.y) : "l"(v));
    return f;
}

/* ------------------------------ prep ------------------------------ */
__global__ void copy_slots(const float* __restrict__ prev) {
    int i = blockIdx.x * blockDim.x + threadIdx.x;
    d_slots[i] = prev[i];
}

__global__ void prep_wp(const float* __restrict__ Wk, const float* __restrict__ Wv,
                        const float* __restrict__ g_in) {
    int f = blockIdx.x, h = threadIdx.x;
    float w = (h < DD) ? Wk[h*FF + f] : Wv[(h-DD)*FF + f];
    d_wp[f*HKV + h] = g_in[f] * w;
}

__global__ void prep_c(const float* __restrict__ Wk, const float* __restrict__ Wv,
                       const float* __restrict__ b_in) {
    int h = threadIdx.x;
    float s1 = 0.f, s0 = 0.f;
    for (int f = 0; f < FF; f++) {
        s1 += d_wp[f*HKV + h];
        float w = (h < DD) ? Wk[h*FF + f] : Wv[(h-DD)*FF + f];
        s0 += b_in[f] * w;
    }
    d_c1[h] = s1; d_c0[h] = s0;
}

__global__ void transpose_sel(const float* __restrict__ src, int R, int C, int which) {
    float* dst = (which == 0) ? d_wqT : (which == 1) ? d_wihT :
                 (which == 2) ? d_whhT : (which == 3) ? d_w1T : d_w2T;
    int idx = blockIdx.x * blockDim.x + threadIdx.x;
    if (idx < R * C) {
        int r = idx / C, c = idx - r * C;
        dst[c * R + r] = src[idx];
    }
}

/* ---------------- fused LN + KV GEMM: 131072 x 512, K=768 ----------------
 * C[r][h] = rs*( (X@Wp)[r][h] - m*c1[h] ) + c0[h]
 * BM=128 BN=128 BK=16, 256 threads.
 * Microtile 16(M) x 4(N), M-pairs packed into 64-bit f32x2 accumulators:
 * per k-step 32 fma2 instead of 64 FFMA (2x fma-pipe throughput). */
__launch_bounds__(256)
__global__ void gemm_kv(const float* __restrict__ X) {
    __shared__ float As[16][128];
    __shared__ float Bs[16][128];
    __shared__ float m_s[128], r_s[128], c1s[128], c0s[128];

    int tid = threadIdx.x;
    int c0b = blockIdx.x * 128;
    int r0  = blockIdx.y * 128;
    int tx = tid & 31, ty = tid >> 5;          /* cols tx*4, rows ty*16 */
    int arow = tid >> 2, ac4 = tid & 3;        /* A loads: rows arow, arow+64 */
    int brow = tid >> 5, bc4 = tid & 31;       /* B loads: rows brow, brow+8 */

    if (tid < 128) { c1s[tid] = d_c1[c0b + tid]; c0s[tid] = d_c0[c0b + tid]; }

    unsigned long long acc[8][4];
#pragma unroll
    for (int p = 0; p < 8; p++)
#pragma unroll
        for (int j = 0; j < 4; j++) acc[p][j] = 0ull;

    float ps0 = 0.f, pq0 = 0.f, ps1 = 0.f, pq1 = 0.f;

    for (int k0 = 0; k0 < FF; k0 += 16) {
        __syncthreads();
        float4 a0 = *(const float4*)&X[(size_t)(r0 + arow)      * FF + k0 + ac4 * 4];
        float4 a1 = *(const float4*)&X[(size_t)(r0 + arow + 64) * FF + k0 + ac4 * 4];
        As[ac4*4+0][arow] = a0.x; As[ac4*4+1][arow] = a0.y;
        As[ac4*4+2][arow] = a0.z; As[ac4*4+3][arow] = a0.w;
        As[ac4*4+0][arow+64] = a1.x; As[ac4*4+1][arow+64] = a1.y;
        As[ac4*4+2][arow+64] = a1.z; As[ac4*4+3][arow+64] = a1.w;
        ps0 += a0.x + a0.y + a0.z + a0.w;
        pq0 += a0.x*a0.x + a0.y*a0.y + a0.z*a0.z + a0.w*a0.w;
        ps1 += a1.x + a1.y + a1.z + a1.w;
        pq1 += a1.x*a1.x + a1.y*a1.y + a1.z*a1.z + a1.w*a1.w;

        float4 b0 = *(const float4*)&d_wp[(k0 + brow)     * HKV + c0b + bc4 * 4];
        float4 b1 = *(const float4*)&d_wp[(k0 + brow + 8) * HKV + c0b + bc4 * 4];
        *(float4*)&Bs[brow][bc4*4]   = b0;
        *(float4*)&Bs[brow+8][bc4*4] = b1;
        __syncthreads();

#pragma unroll
        for (int kk = 0; kk < 16; kk++) {
            /* all 32 lanes of a warp share ty -> As reads are broadcast (free);
             * Bs: each lane reads its own 16B chunk -> conflict-free */
            const ulonglong2* ap = (const ulonglong2*)&As[kk][ty * 16];
            ulonglong2 u0 = ap[0], u1 = ap[1], u2 = ap[2], u3 = ap[3];
            unsigned long long av[8] = {u0.x, u0.y, u1.x, u1.y, u2.x, u2.y, u3.x, u3.y};
            float4 b4 = *(const float4*)&Bs[kk][tx * 4];
            unsigned long long bd0 = dup2(b4.x), bd1 = dup2(b4.y),
                               bd2 = dup2(b4.z), bd3 = dup2(b4.w);
#pragma unroll
            for (int p = 0; p < 8; p++) {
                fma2(acc[p][0], av[p], bd0);
                fma2(acc[p][1], av[p], bd1);
                fma2(acc[p][2], av[p], bd2);
                fma2(acc[p][3], av[p], bd3);
            }
        }
    }

    /* LN stats: reduce over the 4 lanes sharing each A row */
    ps0 += __shfl_xor_sync(0xffffffffu, ps0, 1); ps0 += __shfl_xor_sync(0xffffffffu, ps0, 2);
    pq0 += __shfl_xor_sync(0xffffffffu, pq0, 1); pq0 += __shfl_xor_sync(0xffffffffu, pq0, 2);
    ps1 += __shfl_xor_sync(0xffffffffu, ps1, 1); ps1 += __shfl_xor_sync(0xffffffffu, ps1, 2);
    pq1 += __shfl_xor_sync(0xffffffffu, pq1, 1); pq1 += __shfl_xor_sync(0xffffffffu, pq1, 2);
    if ((tid & 3) == 0) {
        float m0 = ps0 * (1.f/FF);
        m_s[arow] = m0;    r_s[arow]    = rsqrtf(pq0*(1.f/FF) - m0*m0 + 1e-5f);
        float m1 = ps1 * (1.f/FF);
        m_s[arow+64] = m1; r_s[arow+64] = rsqrtf(pq1*(1.f/FF) - m1*m1 + 1e-5f);
    }
    __syncthreads();

    float cc0 = c1s[tx*4+0], cc1 = c1s[tx*4+1], cc2 = c1s[tx*4+2], cc3 = c1s[tx*4+3];
    float d0 = c0s[tx*4+0], d1 = c0s[tx*4+1], d2 = c0s[tx*4+2], d3 = c0s[tx*4+3];
#pragma unroll
    for (int p = 0; p < 8; p++) {
        float2 f0 = unpk(acc[p][0]), f1 = unpk(acc[p][1]),
               f2 = unpk(acc[p][2]), f3 = unpk(acc[p][3]);
        int r = ty * 16 + 2 * p;
        {
            float m = m_s[r], rs = r_s[r];
            float4 o;
            o.x = rs * (f0.x - m * cc0) + d0;
            o.y = rs * (f1.x - m * cc1) + d1;
            o.z = rs * (f2.x - m * cc2) + d2;
            o.w = rs * (f3.x - m * cc3) + d3;
            *(float4*)&d_kv[(size_t)(r0 + r) * HKV + c0b + tx * 4] = o;
        }
        {
            float m = m_s[r+1], rs = r_s[r+1];
            float4 o;
            o.x = rs * (f0.y - m * cc0) + d0;
            o.y = rs * (f1.y - m * cc1) + d1;
            o.z = rs * (f2.y - m * cc2) + d2;
            o.w = rs * (f3.y - m * cc3) + d3;
            *(float4*)&d_kv[(size_t)(r0 + r + 1) * HKV + c0b + tx * 4] = o;
        }
    }
}

/* ---------------- slots LN + q projection (q *= SCALE) ---------------- */
__global__ void slots_q(const float* __restrict__ g_s, const float* __restrict__ b_s) {
    __shared__ float lnr[DD];
    __shared__ float ws[8], wq[8];
    int row = blockIdx.x, t = threadIdx.x;
    float x = d_slots[row * DD + t];
    float s = x, q2 = x * x;
#pragma unroll
    for (int o = 16; o; o >>= 1) {
        s  += __shfl_xor_sync(0xffffffffu, s, o);
        q2 += __shfl_xor_sync(0xffffffffu, q2, o);
    }
    if ((t & 31) == 0) { ws[t >> 5] = s; wq[t >> 5] = q2; }
    __syncthreads();
    float S = 0.f, Q = 0.f;
#pragma unroll
    for (int i = 0; i < 8; i++) { S += ws[i]; Q += wq[i]; }
    float m = S * (1.f/DD);
    float rst = rsqrtf(Q * (1.f/DD) - m * m + 1e-5f);
    lnr[t] = (x - m) * rst * g_s[t] + b_s[t];
    __syncthreads();
    float acc = 0.f;
#pragma unroll 8
    for (int d = 0; d < DD; d++) acc += lnr[d] * d_wqT[d * DD + t];
    d_q[row * DD + t] = acc * QSCALE;
}

__global__ void zero_urs() {
    int i = blockIdx.x * blockDim.x + threadIdx.x;
    if (i < SROWS) d_rowsum[i] = 0.f;
    d_updates[i] = 0.f;
}

/* -------- logits + softmax over K + rowsum; 128 thr, 512 n/block -------- */
__launch_bounds__(128)
__global__ void attn_kernel(float* __restrict__ attn_out) {
    __shared__ float qs[KS * DD];
    __shared__ float ks[16][516];
    int b = blockIdx.y;
    int n0 = blockIdx.x * 512;
    int tid = threadIdx.x;

    for (int i = tid; i < KS * DD; i += 128) qs[i] = d_q[b * KS * DD + i];

    float acc[KS][4];
#pragma unroll
    for (int s = 0; s < KS; s++)
#pragma unroll
        for (int j = 0; j < 4; j++) acc[s][j] = 0.f;

    for (int h0 = 0; h0 < DD; h0 += 16) {
        __syncthreads();
#pragma unroll
        for (int j = 0; j < 16; j++) {
            int id = tid + j * 128;
            int row = id >> 2, c4 = id & 3;
            float4 v = *(const float4*)&d_kv[(size_t)(b * NN + n0 + row) * HKV + h0 + c4 * 4];
            ks[c4*4+0][row] = v.x; ks[c4*4+1][row] = v.y;
            ks[c4*4+2][row] = v.z; ks[c4*4+3][row] = v.w;
        }
        __syncthreads();
#pragma unroll
        for (int hh = 0; hh < 16; hh++) {
            float4 kv = *(const float4*)&ks[hh][tid * 4];
#pragma unroll
            for (int s = 0; s < KS; s++) {
                float q = qs[s * DD + h0 + hh];
                acc[s][0] += q * kv.x; acc[s][1] += q * kv.y;
                acc[s][2] += q * kv.z; acc[s][3] += q * kv.w;
            }
        }
    }
    int nb = n0 + tid * 4;
    float rsum[KS];
#pragma unroll
    for (int s = 0; s < KS; s++) rsum[s] = 0.f;
#pragma unroll
    for (int j = 0; j < 4; j++) {
        float mx = acc[0][j];
#pragma unroll
        for (int s = 1; s < KS; s++) mx = fmaxf(mx, acc[s][j]);
        float den = 0.f;
#pragma unroll
        for (int s = 0; s < KS; s++) { acc[s][j] = __expf(acc[s][j] - mx); den += acc[s][j]; }
        float inv = 1.f / den;
#pragma unroll
        for (int s = 0; s < KS; s++) { acc[s][j] *= inv; rsum[s] += acc[s][j]; }
    }
#pragma unroll
    for (int s = 0; s < KS; s++) {
        float4 o = make_float4(acc[s][0], acc[s][1], acc[s][2], acc[s][3]);
        *(float4*)&attn_out[(size_t)(b * KS + s) * NN + nb] = o;
    }
#pragma unroll
    for (int s = 0; s < KS; s++) {
        float v = rsum[s];
#pragma unroll
        for (int o = 16; o; o >>= 1) v += __shfl_xor_sync(0xffffffffu, v, o);
        if ((tid & 31) == 0) atomicAdd(&d_rowsum[b * KS + s], v);
    }
}

/* ---------------- updates += attn @ v (unnormalized) ---------------- */
__launch_bounds__(256)
__global__ void updates_kernel(const float* __restrict__ attn_in) {
    __shared__ float vs[32][256];
    __shared__ float as[KS][32];
    int b = blockIdx.y;
    int n0 = blockIdx.x * 512;
    int tid = threadIdx.x;
    int s = tid >> 5, lane = tid & 31, d8 = lane * 8;
    float acc[8];
#pragma unroll
    for (int i = 0; i < 8; i++) acc[i] = 0.f;
    for (int n1 = 0; n1 < 512; n1 += 32) {
        __syncthreads();
#pragma unroll
        for (int j = 0; j < 8; j++) {
            int id = tid + j * 256;
            int row = id >> 6, c4 = id & 63;
            *(float4*)&vs[row][c4*4] =
                *(const float4*)&d_kv[(size_t)(b * NN + n0 + n1 + row) * HKV + DD + c4 * 4];
        }
        as[s][lane] = attn_in[(size_t)(b * KS + s) * NN + n0 + n1 + lane];
        __syncthreads();
#pragma unroll
        for (int j = 0; j < 32; j++) {
            float a = as[s][j];
            float4 v0 = *(const float4*)&vs[j][d8];
            float4 v1 = *(const float4*)&vs[j][d8 + 4];
            acc[0] += a * v0.x; acc[1] += a * v0.y; acc[2] += a * v0.z; acc[3] += a * v0.w;
            acc[4] += a * v1.x; acc[5] += a * v1.y; acc[6] += a * v1.z; acc[7] += a * v1.w;
        }
    }
#pragma unroll
    for (int i = 0; i < 8; i++)
        atomicAdd(&d_updates[(b * KS + s) * DD + d8 + i], acc[i]);
}

/* ---------------- GRU cell: one block per slot row ---------------- */
__global__ void gru_kernel(const float* __restrict__ b_ih, const float* __restrict__ b_hh) {
    __shared__ float us[DD], ss[DD];
    int row = blockIdx.x, t = threadIdx.x;
    float inv = 1.f / (d_rowsum[row] + EPSN);
    us[t] = d_updates[row * DD + t] * inv;
    ss[t] = d_slots[row * DD + t];
    __syncthreads();
    float gir = 0.f, giz = 0.f, gin = 0.f, ghr = 0.f, ghz = 0.f, ghn = 0.f;
#pragma unroll 4
    for (int d = 0; d < DD; d++) {
        float u = us[d], sv = ss[d];
        const float* wi = &d_wihT[d * (3*DD)];
        const float* wh = &d_whhT[d * (3*DD)];
        gir += u * wi[t];        ghr += sv * wh[t];
        giz += u * wi[t + DD];   ghz += sv * wh[t + DD];
        gin += u * wi[t + 2*DD]; ghn += sv * wh[t + 2*DD];
    }
    gir += b_ih[t];        ghr += b_hh[t];
    giz += b_ih[t + DD];   ghz += b_hh[t + DD];
    gin += b_ih[t + 2*DD]; ghn += b_hh[t + 2*DD];
    float r = sigf(gir + ghr);
    float z = sigf(giz + ghz);
    float n = tanhf(gin + r * ghn);
    d_h[row * DD + t] = (1.f - z) * n + z * ss[t];
}

/* ---------------- MLP (LN -> W1,relu -> W2) + residual ---------------- */
__global__ void mlp_kernel(const float* __restrict__ g_m, const float* __restrict__ b_m,
                           const float* __restrict__ b1, const float* __restrict__ b2) {
    __shared__ float lnh[DD], m1[DD];
    __shared__ float ws[8], wq[8];
    int row = blockIdx.x, t = threadIdx.x;
    float h = d_h[row * DD + t];
    float s = h, q2 = h * h;
#pragma unroll
    for (int o = 16; o; o >>= 1) {
        s  += __shfl_xor_sync(0xffffffffu, s, o);
        q2 += __shfl_xor_sync(0xffffffffu, q2, o);
    }
    if ((t & 31) == 0) { ws[t >> 5] = s; wq[t >> 5] = q2; }
    __syncthreads();
    float S = 0.f, Q = 0.f;
#pragma unroll
    for (int i = 0; i < 8; i++) { S += ws[i]; Q += wq[i]; }
    float m = S * (1.f/DD);
    float rst = rsqrtf(Q * (1.f/DD) - m * m + 1e-5f);
    lnh[t] = (h - m) * rst * g_m[t] + b_m[t];
    __syncthreads();
    float a1 = 0.f;
#pragma unroll 8
    for (int d = 0; d < DD; d++) a1 += lnh[d] * d_w1T[d * DD + t];
    m1[t] = fmaxf(a1 + b1[t], 0.f);
    __syncthreads();
    float a2 = 0.f;
#pragma unroll 8
    for (int d = 0; d < DD; d++) a2 += m1[d] * d_w2T[d * DD + t];
    d_slots[row * DD + t] = h + a2 + b2[t];
}

/* ---------------- final blend ---------------- */
__global__ void final_out(const float* __restrict__ prev, float* __restrict__ out) {
    int row = blockIdx.x, t = threadIdx.x;
    float mask = sigf(d_rowsum[row] * (1.f / NN));
    out[row * DD + t] = d_slots[row * DD + t] * mask + prev[row * DD + t] * (1.f - mask);
}

/* ------------------------------ launch ------------------------------ */
extern "C" void kernel_launch(void* const* d_in, const int* in_sizes, int n_in,
                              void* d_out, int out_size) {
    const float* features = (const float*)d_in[0];
    const float* prev     = (const float*)d_in[1];
    const float* g_in     = (const float*)d_in[2];
    const float* b_in     = (const float*)d_in[3];
    const float* g_s      = (const float*)d_in[4];
    const float* b_s      = (const float*)d_in[5];
    const float* g_m      = (const float*)d_in[6];
    const float* b_m      = (const float*)d_in[7];
    const float* Wq       = (const float*)d_in[8];
    const float* Wk       = (const float*)d_in[9];
    const float* Wv       = (const float*)d_in[10];
    const float* W_ih     = (const float*)d_in[11];
    const float* W_hh     = (const float*)d_in[12];
    const float* b_ih     = (const float*)d_in[13];
    const float* b_hh     = (const float*)d_in[14];
    const float* W1       = (const float*)d_in[15];
    const float* b1       = (const float*)d_in[16];
    const float* W2       = (const float*)d_in[17];
    const float* b2       = (const float*)d_in[18];
    float* out = (float*)d_out;

    float* attn_scratch = nullptr;
    cudaGetSymbolAddress((void**)&attn_scratch, d_attn);
    float* attn_final = (out_size >= SROWS*DD + SROWS*NN) ? out + SROWS*DD : attn_scratch;

    /* prep */
    copy_slots<<<SROWS*DD/256, 256>>>(prev);
    prep_wp<<<FF, HKV>>>(Wk, Wv, g_in);
    prep_c<<<1, HKV>>>(Wk, Wv, b_in);
    transpose_sel<<<(DD*DD+255)/256, 256>>>(Wq, DD, DD, 0);
    transpose_sel<<<(3*DD*DD+255)/256, 256>>>(W_ih, 3*DD, DD, 1);
    transpose_sel<<<(3*DD*DD+255)/256, 256>>>(W_hh, 3*DD, DD, 2);
    transpose_sel<<<(DD*DD+255)/256, 256>>>(W1, DD, DD, 3);
    transpose_sel<<<(DD*DD+255)/256, 256>>>(W2, DD, DD, 4);

    /* big fused LN + KV projection */
    {
        dim3 grid(HKV/128, NROWS/128);
        gemm_kv<<<grid, 256>>>(features);
    }

    /* 3 slot-attention iterations */
    for (int it = 0; it < 3; it++) {
        slots_q<<<SROWS, DD>>>(g_s, b_s);
        zero_urs<<<SROWS*DD/256, 256>>>();
        {
            dim3 g(NN/512, BB);
            attn_kernel<<<g, 128>>>(attn_scratch);
            updates_kernel<<<g, 256>>>(attn_scratch);
        }
        gru_kernel<<<SROWS, DD>>>(b_ih, b_hh);
        mlp_kernel<<<SROWS, DD>>>(g_m, b_m, b1, b2);
    }

    /* final attention + confidence blend */
    slots_q<<<SROWS, DD>>>(g_s, b_s);
    zero_urs<<<SROWS*DD/256, 256>>>();
    {
        dim3 g(NN/512, BB);
        attn_kernel<<<g, 128>>>(attn_final);
    }
    final_out<<<SROWS, DD>>>(prev, out);
}

// round 9
// speedup vs baseline: 1.3170x; 1.3086x over previous
#include <cuda_runtime.h>
#include <cuda_bf16.h>
#include <math.h>
#include <stdint.h>

#define BB 32
#define NN 4096
#define FF 768
#define DD 256
#define KS 8
#define HKV 512
#define NROWS (BB*NN)
#define SROWS (BB*KS)
#define EPSN 1e-8f
#define QSCALE 0.0625f

/* ------------------ device scratch (static, no allocs) ------------------ */
static __device__ float d_kv[(size_t)NROWS*HKV];   /* k|v per row, 268MB */
static __device__ __nv_bfloat16 d_wphi[HKV*FF];
static __device__ __nv_bfloat16 d_wplo[HKV*FF];
static __device__ float d_c1[HKV];
static __device__ float d_c0[HKV];
static __device__ float d_wqT[DD*DD];
static __device__ float d_wihT[DD*3*DD];
static __device__ float d_whhT[DD*3*DD];
static __device__ float d_w1T[DD*DD];
static __device__ float d_w2T[DD*DD];
static __device__ float d_q[SROWS*DD];
static __device__ float d_attn[(size_t)SROWS*NN];
static __device__ float d_rowsum[SROWS];
static __device__ float d_updates[SROWS*DD];
static __device__ float d_h[SROWS*DD];
static __device__ float d_slots[SROWS*DD];

__device__ __forceinline__ float sigf(float x) { return 1.f / (1.f + __expf(-x)); }

__device__ __forceinline__ uint32_t smem_u32(const void* p) {
    uint32_t a;
    asm("{ .reg .u64 t; cvta.to.shared.u64 t, %1; cvt.u32.u64 %0, t; }" : "=r"(a) : "l"(p));
    return a;
}
__device__ __forceinline__ void ldm_x4(uint32_t* r, uint32_t addr) {
    asm volatile("ldmatrix.sync.aligned.m8n8.x4.shared.b16 {%0,%1,%2,%3}, [%4];"
        : "=r"(r[0]), "=r"(r[1]), "=r"(r[2]), "=r"(r[3]) : "r"(addr));
}
__device__ __forceinline__ void mma_bf16(float* d, const uint32_t* a,
                                         uint32_t b0, uint32_t b1) {
    asm volatile("mma.sync.aligned.m16n8k16.row.col.f32.bf16.bf16.f32 "
        "{%0,%1,%2,%3}, {%4,%5,%6,%7}, {%8,%9}, {%0,%1,%2,%3};"
        : "+f"(d[0]), "+f"(d[1]), "+f"(d[2]), "+f"(d[3])
        : "r"(a[0]), "r"(a[1]), "r"(a[2]), "r"(a[3]), "r"(b0), "r"(b1));
}
__device__ __forceinline__ uint32_t pk2(__nv_bfloat16 a, __nv_bfloat16 b) {
    return (uint32_t)__bfloat16_as_ushort(a) | ((uint32_t)__bfloat16_as_ushort(b) << 16);
}

/* ------------------------------ prep ------------------------------ */
__global__ void copy_slots(const float* __restrict__ prev) {
    int i = blockIdx.x * blockDim.x + threadIdx.x;
    d_slots[i] = prev[i];
}

/* Wp[h][f] = g_in[f] * W[h][f], split to bf16 hi/lo */
__global__ void prep_wsplit(const float* __restrict__ Wk, const float* __restrict__ Wv,
                            const float* __restrict__ g_in) {
    int h = blockIdx.x, f = threadIdx.x;
    float w = g_in[f] * ((h < DD) ? Wk[h*FF + f] : Wv[(h-DD)*FF + f]);
    __nv_bfloat16 hi = __float2bfloat16_rn(w);
    float lo = w - __bfloat162float(hi);
    d_wphi[h*FF + f] = hi;
    d_wplo[h*FF + f] = __float2bfloat16_rn(lo);
}

__global__ void prep_c(const float* __restrict__ Wk, const float* __restrict__ Wv,
                       const float* __restrict__ g_in, const float* __restrict__ b_in) {
    __shared__ float r1[8], r0s[8];
    int h = blockIdx.x, t = threadIdx.x;
    const float* w = (h < DD) ? &Wk[h*FF] : &Wv[(h-DD)*FF];
    float s1 = 0.f, s0 = 0.f;
    for (int f = t; f < FF; f += 256) {
        float wv = w[f];
        s1 += g_in[f] * wv;
        s0 += b_in[f] * wv;
    }
#pragma unroll
    for (int o = 16; o; o >>= 1) {
        s1 += __shfl_xor_sync(0xffffffffu, s1, o);
        s0 += __shfl_xor_sync(0xffffffffu, s0, o);
    }
    if ((t & 31) == 0) { r1[t >> 5] = s1; r0s[t >> 5] = s0; }
    __syncthreads();
    if (t == 0) {
        float a = 0.f, b = 0.f;
#pragma unroll
        for (int i = 0; i < 8; i++) { a += r1[i]; b += r0s[i]; }
        d_c1[h] = a; d_c0[h] = b;
    }
}

__global__ void transpose_sel(const float* __restrict__ src, int R, int C, int which) {
    float* dst = (which == 0) ? d_wqT : (which == 1) ? d_wihT :
                 (which == 2) ? d_whhT : (which == 3) ? d_w1T : d_w2T;
    int idx = blockIdx.x * blockDim.x + threadIdx.x;
    if (idx < R * C) {
        int r = idx / C, c = idx - r * C;
        dst[c * R + r] = src[idx];
    }
}

/* ------- fused LN + KV GEMM via mma.sync (bf16 hi/lo split, HMMA) -------
 * C[r][h] = rs*( (X@Wp^T)[r][h] - m*c1[h] ) + c0[h]
 * Tile 128x128, BK=32, 8 warps (4M x 2N), warp tile 32x64.
 * D += Ahi*Bhi + Alo*Bhi + Ahi*Blo (fp32 accum). */
#define ASTR 40   /* padded bf16 row stride for 32-col tiles */
__launch_bounds__(256)
__global__ void gemm_kv_mma(const float* __restrict__ X) {
    __shared__ __nv_bfloat16 Ah[128*ASTR], Al[128*ASTR];
    __shared__ __nv_bfloat16 Bh[128*ASTR], Bl[128*ASTR];
    __shared__ float m_s[128], r_s[128], c1s[128], c0s[128];

    int tid = threadIdx.x;
    int wid = tid >> 5, lane = tid & 31;
    int c0b = blockIdx.x * 128;
    int r0  = blockIdx.y * 128;

    if (tid < 128) { c1s[tid] = d_c1[c0b + tid]; c0s[tid] = d_c0[c0b + tid]; }

    int arow = tid >> 1, aq = tid & 1;   /* A: row, 16-float half */
    float ps = 0.f, pq = 0.f;

    int wm = wid >> 1, wn = wid & 1;
    int m_off = wm * 32, n_off = wn * 64;

    float acc[2][8][4];
#pragma unroll
    for (int mt = 0; mt < 2; mt++)
#pragma unroll
        for (int nt = 0; nt < 8; nt++)
#pragma unroll
            for (int j = 0; j < 4; j++) acc[mt][nt][j] = 0.f;

    /* ldmatrix lane->address mapping (A, 16x16 tiles) */
    uint32_t a_h_base = smem_u32(Ah) +
        (uint32_t)(((m_off + (lane & 15)) * ASTR + (lane >> 4) * 8) * 2);
    uint32_t a_l_base = smem_u32(Al) +
        (uint32_t)(((m_off + (lane & 15)) * ASTR + (lane >> 4) * 8) * 2);
    int nlane = lane >> 2, klane = (lane & 3) * 2;

    for (int ch = 0; ch < 24; ch++) {
        int k0 = ch * 32;
        __syncthreads();
        /* A tile: coalesced f32 load + stats + split to hi/lo bf16 smem */
        {
            const float* xp = &X[(size_t)(r0 + arow) * FF + k0 + aq * 16];
#pragma unroll
            for (int i = 0; i < 4; i++) {
                float4 a = *(const float4*)&xp[i * 4];
                ps += a.x + a.y + a.z + a.w;
                pq += a.x*a.x + a.y*a.y + a.z*a.z + a.w*a.w;
                __nv_bfloat16 h0 = __float2bfloat16_rn(a.x), h1 = __float2bfloat16_rn(a.y);
                __nv_bfloat16 h2 = __float2bfloat16_rn(a.z), h3 = __float2bfloat16_rn(a.w);
                __nv_bfloat16 l0 = __float2bfloat16_rn(a.x - __bfloat162float(h0));
                __nv_bfloat16 l1 = __float2bfloat16_rn(a.y - __bfloat162float(h1));
                __nv_bfloat16 l2 = __float2bfloat16_rn(a.z - __bfloat162float(h2));
                __nv_bfloat16 l3 = __float2bfloat16_rn(a.w - __bfloat162float(h3));
                int o = arow * ASTR + aq * 16 + i * 4;
                uint2 uh, ul;
                uh.x = pk2(h0, h1); uh.y = pk2(h2, h3);
                ul.x = pk2(l0, l1); ul.y = pk2(l2, l3);
                *(uint2*)&Ah[o] = uh;
                *(uint2*)&Al[o] = ul;
            }
        }
        /* B tile: copy precomputed bf16 hi/lo — FULL 16 elements (2x uint4) */
        {
            size_t g = (size_t)(c0b + arow) * FF + k0 + aq * 16;
            int o = arow * ASTR + aq * 16;
            *(uint4*)&Bh[o]     = *(const uint4*)&d_wphi[g];
            *(uint4*)&Bh[o + 8] = *(const uint4*)&d_wphi[g + 8];
            *(uint4*)&Bl[o]     = *(const uint4*)&d_wplo[g];
            *(uint4*)&Bl[o + 8] = *(const uint4*)&d_wplo[g + 8];
        }
        __syncthreads();

#pragma unroll
        for (int s = 0; s < 2; s++) {
            uint32_t ah[2][4], al[2][4];
#pragma unroll
            for (int mt = 0; mt < 2; mt++) {
                uint32_t off = (uint32_t)(mt * 16 * ASTR * 2 + s * 32);
                ldm_x4(ah[mt], a_h_base + off);
                ldm_x4(al[mt], a_l_base + off);
            }
#pragma unroll
            for (int nt = 0; nt < 8; nt++) {
                int bo = (n_off + nt * 8 + nlane) * ASTR + s * 16 + klane;
                uint32_t bh0 = *(const uint32_t*)&Bh[bo];
                uint32_t bh1 = *(const uint32_t*)&Bh[bo + 8];
                uint32_t bl0 = *(const uint32_t*)&Bl[bo];
                uint32_t bl1 = *(const uint32_t*)&Bl[bo + 8];
#pragma unroll
                for (int mt = 0; mt < 2; mt++) {
                    mma_bf16(acc[mt][nt], ah[mt], bh0, bh1);
                    mma_bf16(acc[mt][nt], al[mt], bh0, bh1);
                    mma_bf16(acc[mt][nt], ah[mt], bl0, bl1);
                }
            }
        }
    }

    /* LN stats: pair (tid, tid^1) shares row arow */
    ps += __shfl_xor_sync(0xffffffffu, ps, 1);
    pq += __shfl_xor_sync(0xffffffffu, pq, 1);
    if (aq == 0) {
        float m = ps * (1.f / FF);
        m_s[arow] = m;
        r_s[arow] = rsqrtf(pq * (1.f / FF) - m * m + 1e-5f);
    }
    __syncthreads();

    /* epilogue: apply LN fold, write fp32 */
    int g = lane >> 2, c2 = (lane & 3) * 2;
#pragma unroll
    for (int mt = 0; mt < 2; mt++) {
#pragma unroll
        for (int rr = 0; rr < 2; rr++) {
            int row = m_off + mt * 16 + g + rr * 8;
            float m = m_s[row], rs = r_s[row];
            float* dst = &d_kv[(size_t)(r0 + row) * HKV + c0b];
#pragma unroll
            for (int nt = 0; nt < 8; nt++) {
                int col = n_off + nt * 8 + c2;
                float2 o;
                o.x = rs * (acc[mt][nt][rr*2+0] - m * c1s[col])     + c0s[col];
                o.y = rs * (acc[mt][nt][rr*2+1] - m * c1s[col + 1]) + c0s[col + 1];
                *(float2*)&dst[col] = o;
            }
        }
    }
}

/* ---------------- slots LN + q projection (q *= SCALE) ---------------- */
__global__ void slots_q(const float* __restrict__ g_s, const float* __restrict__ b_s) {
    __shared__ float lnr[DD];
    __shared__ float ws[8], wq[8];
    int row = blockIdx.x, t = threadIdx.x;
    float x = d_slots[row * DD + t];
    float s = x, q2 = x * x;
#pragma unroll
    for (int o = 16; o; o >>= 1) {
        s  += __shfl_xor_sync(0xffffffffu, s, o);
        q2 += __shfl_xor_sync(0xffffffffu, q2, o);
    }
    if ((t & 31) == 0) { ws[t >> 5] = s; wq[t >> 5] = q2; }
    __syncthreads();
    float S = 0.f, Q = 0.f;
#pragma unroll
    for (int i = 0; i < 8; i++) { S += ws[i]; Q += wq[i]; }
    float m = S * (1.f/DD);
    float rst = rsqrtf(Q * (1.f/DD) - m * m + 1e-5f);
    lnr[t] = (x - m) * rst * g_s[t] + b_s[t];
    __syncthreads();
    float acc = 0.f;
#pragma unroll 8
    for (int d = 0; d < DD; d++) acc += lnr[d] * d_wqT[d * DD + t];
    d_q[row * DD + t] = acc * QSCALE;
}

__global__ void zero_urs() {
    int i = blockIdx.x * blockDim.x + threadIdx.x;
    if (i < SROWS) d_rowsum[i] = 0.f;
    d_updates[i] = 0.f;
}

/* -------- logits + softmax over K + rowsum; 128 thr, 512 n/block -------- */
__launch_bounds__(128)
__global__ void attn_kernel(float* __restrict__ attn_out) {
    __shared__ float qs[KS * DD];
    __shared__ float ks[16][516];
    int b = blockIdx.y;
    int n0 = blockIdx.x * 512;
    int tid = threadIdx.x;

    for (int i = tid; i < KS * DD; i += 128) qs[i] = d_q[b * KS * DD + i];

    float acc[KS][4];
#pragma unroll
    for (int s = 0; s < KS; s++)
#pragma unroll
        for (int j = 0; j < 4; j++) acc[s][j] = 0.f;

    for (int h0 = 0; h0 < DD; h0 += 16) {
        __syncthreads();
#pragma unroll
        for (int j = 0; j < 16; j++) {
            int id = tid + j * 128;
            int row = id >> 2, c4 = id & 3;
            float4 v = *(const float4*)&d_kv[(size_t)(b * NN + n0 + row) * HKV + h0 + c4 * 4];
            ks[c4*4+0][row] = v.x; ks[c4*4+1][row] = v.y;
            ks[c4*4+2][row] = v.z; ks[c4*4+3][row] = v.w;
        }
        __syncthreads();
#pragma unroll
        for (int hh = 0; hh < 16; hh++) {
            float4 kv = *(const float4*)&ks[hh][tid * 4];
#pragma unroll
            for (int s = 0; s < KS; s++) {
                float q = qs[s * DD + h0 + hh];
                acc[s][0] += q * kv.x; acc[s][1] += q * kv.y;
                acc[s][2] += q * kv.z; acc[s][3] += q * kv.w;
            }
        }
    }
    int nb = n0 + tid * 4;
    float rsum[KS];
#pragma unroll
    for (int s = 0; s < KS; s++) rsum[s] = 0.f;
#pragma unroll
    for (int j = 0; j < 4; j++) {
        float mx = acc[0][j];
#pragma unroll
        for (int s = 1; s < KS; s++) mx = fmaxf(mx, acc[s][j]);
        float den = 0.f;
#pragma unroll
        for (int s = 0; s < KS; s++) { acc[s][j] = __expf(acc[s][j] - mx); den += acc[s][j]; }
        float inv = 1.f / den;
#pragma unroll
        for (int s = 0; s < KS; s++) { acc[s][j] *= inv; rsum[s] += acc[s][j]; }
    }
#pragma unroll
    for (int s = 0; s < KS; s++) {
        float4 o = make_float4(acc[s][0], acc[s][1], acc[s][2], acc[s][3]);
        *(float4*)&attn_out[(size_t)(b * KS + s) * NN + nb] = o;
    }
#pragma unroll
    for (int s = 0; s < KS; s++) {
        float v = rsum[s];
#pragma unroll
        for (int o = 16; o; o >>= 1) v += __shfl_xor_sync(0xffffffffu, v, o);
        if ((tid & 31) == 0) atomicAdd(&d_rowsum[b * KS + s], v);
    }
}

/* ---------------- updates += attn @ v (unnormalized) ---------------- */
__launch_bounds__(256)
__global__ void updates_kernel(const float* __restrict__ attn_in) {
    __shared__ float vs[32][256];
    __shared__ float as[KS][32];
    int b = blockIdx.y;
    int n0 = blockIdx.x * 512;
    int tid = threadIdx.x;
    int s = tid >> 5, lane = tid & 31, d8 = lane * 8;
    float acc[8];
#pragma unroll
    for (int i = 0; i < 8; i++) acc[i] = 0.f;
    for (int n1 = 0; n1 < 512; n1 += 32) {
        __syncthreads();
#pragma unroll
        for (int j = 0; j < 8; j++) {
            int id = tid + j * 256;
            int row = id >> 6, c4 = id & 63;
            *(float4*)&vs[row][c4*4] =
                *(const float4*)&d_kv[(size_t)(b * NN + n0 + n1 + row) * HKV + DD + c4 * 4];
        }
        as[s][lane] = attn_in[(size_t)(b * KS + s) * NN + n0 + n1 + lane];
        __syncthreads();
#pragma unroll
        for (int j = 0; j < 32; j++) {
            float a = as[s][j];
            float4 v0 = *(const float4*)&vs[j][d8];
            float4 v1 = *(const float4*)&vs[j][d8 + 4];
            acc[0] += a * v0.x; acc[1] += a * v0.y; acc[2] += a * v0.z; acc[3] += a * v0.w;
            acc[4] += a * v1.x; acc[5] += a * v1.y; acc[6] += a * v1.z; acc[7] += a * v1.w;
        }
    }
#pragma unroll
    for (int i = 0; i < 8; i++)
        atomicAdd(&d_updates[(b * KS + s) * DD + d8 + i], acc[i]);
}

/* ---------------- GRU cell: one block per slot row ---------------- */
__global__ void gru_kernel(const float* __restrict__ b_ih, const float* __restrict__ b_hh) {
    __shared__ float us[DD], ss[DD];
    int row = blockIdx.x, t = threadIdx.x;
    float inv = 1.f / (d_rowsum[row] + EPSN);
    us[t] = d_updates[row * DD + t] * inv;
    ss[t] = d_slots[row * DD + t];
    __syncthreads();
    float gir = 0.f, giz = 0.f, gin = 0.f, ghr = 0.f, ghz = 0.f, ghn = 0.f;
#pragma unroll 4
    for (int d = 0; d < DD; d++) {
        float u = us[d], sv = ss[d];
        const float* wi = &d_wihT[d * (3*DD)];
        const float* wh = &d_whhT[d * (3*DD)];
        gir += u * wi[t];        ghr += sv * wh[t];
        giz += u * wi[t + DD];   ghz += sv * wh[t + DD];
        gin += u * wi[t + 2*DD]; ghn += sv * wh[t + 2*DD];
    }
    gir += b_ih[t];        ghr += b_hh[t];
    giz += b_ih[t + DD];   ghz += b_hh[t + DD];
    gin += b_ih[t + 2*DD]; ghn += b_hh[t + 2*DD];
    float r = sigf(gir + ghr);
    float z = sigf(giz + ghz);
    float n = tanhf(gin + r * ghn);
    d_h[row * DD + t] = (1.f - z) * n + z * ss[t];
}

/* ---------------- MLP (LN -> W1,relu -> W2) + residual ---------------- */
__global__ void mlp_kernel(const float* __restrict__ g_m, const float* __restrict__ b_m,
                           const float* __restrict__ b1, const float* __restrict__ b2) {
    __shared__ float lnh[DD], m1[DD];
    __shared__ float ws[8], wq[8];
    int row = blockIdx.x, t = threadIdx.x;
    float h = d_h[row * DD + t];
    float s = h, q2 = h * h;
#pragma unroll
    for (int o = 16; o; o >>= 1) {
        s  += __shfl_xor_sync(0xffffffffu, s, o);
        q2 += __shfl_xor_sync(0xffffffffu, q2, o);
    }
    if ((t & 31) == 0) { ws[t >> 5] = s; wq[t >> 5] = q2; }
    __syncthreads();
    float S = 0.f, Q = 0.f;
#pragma unroll
    for (int i = 0; i < 8; i++) { S += ws[i]; Q += wq[i]; }
    float m = S * (1.f/DD);
    float rst = rsqrtf(Q * (1.f/DD) - m * m + 1e-5f);
    lnh[t] = (h - m) * rst * g_m[t] + b_m[t];
    __syncthreads();
    float a1 = 0.f;
#pragma unroll 8
    for (int d = 0; d < DD; d++) a1 += lnh[d] * d_w1T[d * DD + t];
    m1[t] = fmaxf(a1 + b1[t], 0.f);
    __syncthreads();
    float a2 = 0.f;
#pragma unroll 8
    for (int d = 0; d < DD; d++) a2 += m1[d] * d_w2T[d * DD + t];
    d_slots[row * DD + t] = h + a2 + b2[t];
}

/* ---------------- final blend ---------------- */
__global__ void final_out(const float* __restrict__ prev, float* __restrict__ out) {
    int row = blockIdx.x, t = threadIdx.x;
    float mask = sigf(d_rowsum[row] * (1.f / NN));
    out[row * DD + t] = d_slots[row * DD + t] * mask + prev[row * DD + t] * (1.f - mask);
}

/* ------------------------------ launch ------------------------------ */
extern "C" void kernel_launch(void* const* d_in, const int* in_sizes, int n_in,
                              void* d_out, int out_size) {
    const float* features = (const float*)d_in[0];
    const float* prev     = (const float*)d_in[1];
    const float* g_in     = (const float*)d_in[2];
    const float* b_in     = (const float*)d_in[3];
    const float* g_s      = (const float*)d_in[4];
    const float* b_s      = (const float*)d_in[5];
    const float* g_m      = (const float*)d_in[6];
    const float* b_m      = (const float*)d_in[7];
    const float* Wq       = (const float*)d_in[8];
    const float* Wk       = (const float*)d_in[9];
    const float* Wv       = (const float*)d_in[10];
    const float* W_ih     = (const float*)d_in[11];
    const float* W_hh     = (const float*)d_in[12];
    const float* b_ih     = (const float*)d_in[13];
    const float* b_hh     = (const float*)d_in[14];
    const float* W1       = (const float*)d_in[15];
    const float* b1       = (const float*)d_in[16];
    const float* W2       = (const float*)d_in[17];
    const float* b2       = (const float*)d_in[18];
    float* out = (float*)d_out;

    float* attn_scratch = nullptr;
    cudaGetSymbolAddress((void**)&attn_scratch, d_attn);
    /* Output layout: [0, SROWS*DD) = slots_out, [SROWS*DD, +SROWS*NN) = attn_final */
    float* attn_final = (out_size >= SROWS*DD + SROWS*NN) ? out + SROWS*DD : attn_scratch;

    /* prep — ordered so launch #5 (ncu -s 5 -c 1) is the GEMM */
    copy_slots<<<SROWS*DD/256, 256>>>(prev);                       /* 0 */
    prep_wsplit<<<HKV, FF>>>(Wk, Wv, g_in);                        /* 1 */
    prep_c<<<HKV, 256>>>(Wk, Wv, g_in, b_in);                      /* 2 */
    transpose_sel<<<(DD*DD+255)/256, 256>>>(Wq, DD, DD, 0);        /* 3 */
    transpose_sel<<<(3*DD*DD+255)/256, 256>>>(W_ih, 3*DD, DD, 1);  /* 4 */
    {
        dim3 grid(HKV/128, NROWS/128);                             /* 5 */
        gemm_kv_mma<<<grid, 256>>>(features);
    }
    transpose_sel<<<(3*DD*DD+255)/256, 256>>>(W_hh, 3*DD, DD, 2);
    transpose_sel<<<(DD*DD+255)/256, 256>>>(W1, DD, DD, 3);
    transpose_sel<<<(DD*DD+255)/256, 256>>>(W2, DD, DD, 4);

    /* 3 slot-attention iterations */
    for (int it = 0; it < 3; it++) {
        slots_q<<<SROWS, DD>>>(g_s, b_s);
        zero_urs<<<SROWS*DD/256, 256>>>();
        {
            dim3 g(NN/512, BB);
            attn_kernel<<<g, 128>>>(attn_scratch);
            updates_kernel<<<g, 256>>>(attn_scratch);
        }
        gru_kernel<<<SROWS, DD>>>(b_ih, b_hh);
        mlp_kernel<<<SROWS, DD>>>(g_m, b_m, b1, b2);
    }

    /* final attention + confidence blend */
    slots_q<<<SROWS, DD>>>(g_s, b_s);
    zero_urs<<<SROWS*DD/256, 256>>>();
    {
        dim3 g(NN/512, BB);
        attn_kernel<<<g, 128>>>(attn_final);
    }
    final_out<<<SROWS, DD>>>(prev, out);
}

// round 10
// speedup vs baseline: 1.4783x; 1.1225x over previous
#include <cuda_runtime.h>
#include <cuda_bf16.h>
#include <cuda_fp16.h>
#include <math.h>
#include <stdint.h>

#define BB 32
#define NN 4096
#define FF 768
#define DD 256
#define KS 8
#define HKV 512
#define NROWS (BB*NN)
#define SROWS (BB*KS)
#define EPSN 1e-8f
#define QSCALE 0.0625f

/* ------------------ device scratch (static, no allocs) ------------------ */
static __device__ float d_kv[(size_t)NROWS*HKV];   /* k|v per row, 268MB */
static __device__ __half d_wphi[HKV*FF];
static __device__ __half d_wplo[HKV*FF];
static __device__ float d_c1[HKV];
static __device__ float d_c0[HKV];
static __device__ float d_wqT[DD*DD];
static __device__ float d_wihT[DD*3*DD];
static __device__ float d_whhT[DD*3*DD];
static __device__ float d_w1T[DD*DD];
static __device__ float d_w2T[DD*DD];
static __device__ float d_q[SROWS*DD];
static __device__ float d_attn[(size_t)SROWS*NN];
static __device__ float d_rowsum[SROWS];
static __device__ float d_updates[SROWS*DD];
static __device__ float d_h[SROWS*DD];
static __device__ float d_slots[SROWS*DD];

__device__ __forceinline__ float sigf(float x) { return 1.f / (1.f + __expf(-x)); }

__device__ __forceinline__ uint32_t smem_u32(const void* p) {
    uint32_t a;
    asm("{ .reg .u64 t; cvta.to.shared.u64 t, %1; cvt.u32.u64 %0, t; }" : "=r"(a) : "l"(p));
    return a;
}
__device__ __forceinline__ void ldm_x4(uint32_t* r, uint32_t addr) {
    asm volatile("ldmatrix.sync.aligned.m8n8.x4.shared.b16 {%0,%1,%2,%3}, [%4];"
        : "=r"(r[0]), "=r"(r[1]), "=r"(r[2]), "=r"(r[3]) : "r"(addr));
}
__device__ __forceinline__ void mma_f16(float* d, const uint32_t* a,
                                        uint32_t b0, uint32_t b1) {
    asm volatile("mma.sync.aligned.m16n8k16.row.col.f32.f16.f16.f32 "
        "{%0,%1,%2,%3}, {%4,%5,%6,%7}, {%8,%9}, {%0,%1,%2,%3};"
        : "+f"(d[0]), "+f"(d[1]), "+f"(d[2]), "+f"(d[3])
        : "r"(a[0]), "r"(a[1]), "r"(a[2]), "r"(a[3]), "r"(b0), "r"(b1));
}
__device__ __forceinline__ uint32_t pkh2(__half a, __half b) {
    return (uint32_t)__half_as_ushort(a) | ((uint32_t)__half_as_ushort(b) << 16);
}

/* ------------------------------ prep ------------------------------ */
__global__ void copy_slots(const float* __restrict__ prev) {
    int i = blockIdx.x * blockDim.x + threadIdx.x;
    d_slots[i] = prev[i];
}

/* Wp[h][f] = g_in[f] * W[h][f], split to fp16 hi/lo */
__global__ void prep_wsplit(const float* __restrict__ Wk, const float* __restrict__ Wv,
                            const float* __restrict__ g_in) {
    int h = blockIdx.x, f = threadIdx.x;
    float w = g_in[f] * ((h < DD) ? Wk[h*FF + f] : Wv[(h-DD)*FF + f]);
    __half hi = __float2half_rn(w);
    float lo = w - __half2float(hi);
    d_wphi[h*FF + f] = hi;
    d_wplo[h*FF + f] = __float2half_rn(lo);
}

__global__ void prep_c(const float* __restrict__ Wk, const float* __restrict__ Wv,
                       const float* __restrict__ g_in, const float* __restrict__ b_in) {
    __shared__ float r1[8], r0s[8];
    int h = blockIdx.x, t = threadIdx.x;
    const float* w = (h < DD) ? &Wk[h*FF] : &Wv[(h-DD)*FF];
    float s1 = 0.f, s0 = 0.f;
    for (int f = t; f < FF; f += 256) {
        float wv = w[f];
        s1 += g_in[f] * wv;
        s0 += b_in[f] * wv;
    }
#pragma unroll
    for (int o = 16; o; o >>= 1) {
        s1 += __shfl_xor_sync(0xffffffffu, s1, o);
        s0 += __shfl_xor_sync(0xffffffffu, s0, o);
    }
    if ((t & 31) == 0) { r1[t >> 5] = s1; r0s[t >> 5] = s0; }
    __syncthreads();
    if (t == 0) {
        float a = 0.f, b = 0.f;
#pragma unroll
        for (int i = 0; i < 8; i++) { a += r1[i]; b += r0s[i]; }
        d_c1[h] = a; d_c0[h] = b;
    }
}

__global__ void transpose_sel(const float* __restrict__ src, int R, int C, int which) {
    float* dst = (which == 0) ? d_wqT : (which == 1) ? d_wihT :
                 (which == 2) ? d_whhT : (which == 3) ? d_w1T : d_w2T;
    int idx = blockIdx.x * blockDim.x + threadIdx.x;
    if (idx < R * C) {
        int r = idx / C, c = idx - r * C;
        dst[c * R + r] = src[idx];
    }
}

/* ------- fused LN + KV GEMM via mma.sync (fp16, B hi/lo split) -------
 * C[r][h] = rs*( (X@Wp^T)[r][h] - m*c1[h] ) + c0[h]
 * Tile 128x128, BK=32, 8 warps (4M x 2N), warp tile 32x64.
 * D += A*Bhi + A*Blo (fp32 accum); A single fp16 (err ~2^-12). */
#define ASTR 40   /* padded fp16 row stride for 32-col tiles */
__launch_bounds__(256)
__global__ void gemm_kv_mma(const float* __restrict__ X) {
    __shared__ __half As[128*ASTR];
    __shared__ __half Bh[128*ASTR], Bl[128*ASTR];
    __shared__ float m_s[128], r_s[128], c1s[128], c0s[128];

    int tid = threadIdx.x;
    int wid = tid >> 5, lane = tid & 31;
    int c0b = blockIdx.x * 128;
    int r0  = blockIdx.y * 128;

    if (tid < 128) { c1s[tid] = d_c1[c0b + tid]; c0s[tid] = d_c0[c0b + tid]; }

    int arow = tid >> 1, aq = tid & 1;   /* A: row, 16-elem half */
    float ps = 0.f, pq = 0.f;

    int wm = wid >> 1, wn = wid & 1;
    int m_off = wm * 32, n_off = wn * 64;

    float acc[2][8][4];
#pragma unroll
    for (int mt = 0; mt < 2; mt++)
#pragma unroll
        for (int nt = 0; nt < 8; nt++)
#pragma unroll
            for (int j = 0; j < 4; j++) acc[mt][nt][j] = 0.f;

    /* ldmatrix lane->address mapping (A, 16x16 tiles) */
    uint32_t a_base = smem_u32(As) +
        (uint32_t)(((m_off + (lane & 15)) * ASTR + (lane >> 4) * 8) * 2);
    int nlane = lane >> 2, klane = (lane & 3) * 2;

    for (int ch = 0; ch < 24; ch++) {
        int k0 = ch * 32;
        __syncthreads();
        /* A tile: coalesced f32 load + stats + fp16 convert to smem */
        {
            const float* xp = &X[(size_t)(r0 + arow) * FF + k0 + aq * 16];
#pragma unroll
            for (int i = 0; i < 4; i++) {
                float4 a = *(const float4*)&xp[i * 4];
                ps += a.x + a.y + a.z + a.w;
                pq += a.x*a.x + a.y*a.y + a.z*a.z + a.w*a.w;
                uint2 u;
                u.x = pkh2(__float2half_rn(a.x), __float2half_rn(a.y));
                u.y = pkh2(__float2half_rn(a.z), __float2half_rn(a.w));
                *(uint2*)&As[arow * ASTR + aq * 16 + i * 4] = u;
            }
        }
        /* B tile: copy precomputed fp16 hi/lo — 16 halves = 2x uint4 */
        {
            size_t g = (size_t)(c0b + arow) * FF + k0 + aq * 16;
            int o = arow * ASTR + aq * 16;
            *(uint4*)&Bh[o]     = *(const uint4*)&d_wphi[g];
            *(uint4*)&Bh[o + 8] = *(const uint4*)&d_wphi[g + 8];
            *(uint4*)&Bl[o]     = *(const uint4*)&d_wplo[g];
            *(uint4*)&Bl[o + 8] = *(const uint4*)&d_wplo[g + 8];
        }
        __syncthreads();

#pragma unroll
        for (int s = 0; s < 2; s++) {
            uint32_t af[2][4];
#pragma unroll
            for (int mt = 0; mt < 2; mt++) {
                uint32_t off = (uint32_t)(mt * 16 * ASTR * 2 + s * 32);
                ldm_x4(af[mt], a_base + off);
            }
#pragma unroll
            for (int nt = 0; nt < 8; nt++) {
                int bo = (n_off + nt * 8 + nlane) * ASTR + s * 16 + klane;
                uint32_t bh0 = *(const uint32_t*)&Bh[bo];
                uint32_t bh1 = *(const uint32_t*)&Bh[bo + 8];
                uint32_t bl0 = *(const uint32_t*)&Bl[bo];
                uint32_t bl1 = *(const uint32_t*)&Bl[bo + 8];
#pragma unroll
                for (int mt = 0; mt < 2; mt++) {
                    mma_f16(acc[mt][nt], af[mt], bh0, bh1);
                    mma_f16(acc[mt][nt], af[mt], bl0, bl1);
                }
            }
        }
    }

    /* LN stats: pair (tid, tid^1) shares row arow */
    ps += __shfl_xor_sync(0xffffffffu, ps, 1);
    pq += __shfl_xor_sync(0xffffffffu, pq, 1);
    if (aq == 0) {
        float m = ps * (1.f / FF);
        m_s[arow] = m;
        r_s[arow] = rsqrtf(pq * (1.f / FF) - m * m + 1e-5f);
    }
    __syncthreads();

    /* epilogue: apply LN fold, write fp32 */
    int g = lane >> 2, c2 = (lane & 3) * 2;
#pragma unroll
    for (int mt = 0; mt < 2; mt++) {
#pragma unroll
        for (int rr = 0; rr < 2; rr++) {
            int row = m_off + mt * 16 + g + rr * 8;
            float m = m_s[row], rs = r_s[row];
            float* dst = &d_kv[(size_t)(r0 + row) * HKV + c0b];
#pragma unroll
            for (int nt = 0; nt < 8; nt++) {
                int col = n_off + nt * 8 + c2;
                float2 o;
                o.x = rs * (acc[mt][nt][rr*2+0] - m * c1s[col])     + c0s[col];
                o.y = rs * (acc[mt][nt][rr*2+1] - m * c1s[col + 1]) + c0s[col + 1];
                *(float2*)&dst[col] = o;
            }
        }
    }
}

/* ---------------- slots LN + q projection (q *= SCALE) ---------------- */
__global__ void slots_q(const float* __restrict__ g_s, const float* __restrict__ b_s) {
    __shared__ float lnr[DD];
    __shared__ float ws[8], wq[8];
    int row = blockIdx.x, t = threadIdx.x;
    float x = d_slots[row * DD + t];
    float s = x, q2 = x * x;
#pragma unroll
    for (int o = 16; o; o >>= 1) {
        s  += __shfl_xor_sync(0xffffffffu, s, o);
        q2 += __shfl_xor_sync(0xffffffffu, q2, o);
    }
    if ((t & 31) == 0) { ws[t >> 5] = s; wq[t >> 5] = q2; }
    __syncthreads();
    float S = 0.f, Q = 0.f;
#pragma unroll
    for (int i = 0; i < 8; i++) { S += ws[i]; Q += wq[i]; }
    float m = S * (1.f/DD);
    float rst = rsqrtf(Q * (1.f/DD) - m * m + 1e-5f);
    lnr[t] = (x - m) * rst * g_s[t] + b_s[t];
    __syncthreads();
    float acc = 0.f;
#pragma unroll 8
    for (int d = 0; d < DD; d++) acc += lnr[d] * d_wqT[d * DD + t];
    d_q[row * DD + t] = acc * QSCALE;
}

__global__ void zero_urs() {
    int i = blockIdx.x * blockDim.x + threadIdx.x;
    if (i < SROWS) d_rowsum[i] = 0.f;
    d_updates[i] = 0.f;
}

/* -------- logits + softmax over K + rowsum; 128 thr, 512 n/block -------- */
__launch_bounds__(128)
__global__ void attn_kernel(float* __restrict__ attn_out) {
    __shared__ float qs[KS * DD];
    __shared__ float ks[16][516];
    int b = blockIdx.y;
    int n0 = blockIdx.x * 512;
    int tid = threadIdx.x;

    for (int i = tid; i < KS * DD; i += 128) qs[i] = d_q[b * KS * DD + i];

    float acc[KS][4];
#pragma unroll
    for (int s = 0; s < KS; s++)
#pragma unroll
        for (int j = 0; j < 4; j++) acc[s][j] = 0.f;

    for (int h0 = 0; h0 < DD; h0 += 16) {
        __syncthreads();
#pragma unroll
        for (int j = 0; j < 16; j++) {
            int id = tid + j * 128;
            int row = id >> 2, c4 = id & 3;
            float4 v = *(const float4*)&d_kv[(size_t)(b * NN + n0 + row) * HKV + h0 + c4 * 4];
            ks[c4*4+0][row] = v.x; ks[c4*4+1][row] = v.y;
            ks[c4*4+2][row] = v.z; ks[c4*4+3][row] = v.w;
        }
        __syncthreads();
#pragma unroll
        for (int hh = 0; hh < 16; hh++) {
            float4 kv = *(const float4*)&ks[hh][tid * 4];
#pragma unroll
            for (int s = 0; s < KS; s++) {
                float q = qs[s * DD + h0 + hh];
                acc[s][0] += q * kv.x; acc[s][1] += q * kv.y;
                acc[s][2] += q * kv.z; acc[s][3] += q * kv.w;
            }
        }
    }
    int nb = n0 + tid * 4;
    float rsum[KS];
#pragma unroll
    for (int s = 0; s < KS; s++) rsum[s] = 0.f;
#pragma unroll
    for (int j = 0; j < 4; j++) {
        float mx = acc[0][j];
#pragma unroll
        for (int s = 1; s < KS; s++) mx = fmaxf(mx, acc[s][j]);
        float den = 0.f;
#pragma unroll
        for (int s = 0; s < KS; s++) { acc[s][j] = __expf(acc[s][j] - mx); den += acc[s][j]; }
        float inv = 1.f / den;
#pragma unroll
        for (int s = 0; s < KS; s++) { acc[s][j] *= inv; rsum[s] += acc[s][j]; }
    }
#pragma unroll
    for (int s = 0; s < KS; s++) {
        float4 o = make_float4(acc[s][0], acc[s][1], acc[s][2], acc[s][3]);
        *(float4*)&attn_out[(size_t)(b * KS + s) * NN + nb] = o;
    }
#pragma unroll
    for (int s = 0; s < KS; s++) {
        float v = rsum[s];
#pragma unroll
        for (int o = 16; o; o >>= 1) v += __shfl_xor_sync(0xffffffffu, v, o);
        if ((tid & 31) == 0) atomicAdd(&d_rowsum[b * KS + s], v);
    }
}

/* ---------------- updates += attn @ v (unnormalized) ---------------- */
__launch_bounds__(256)
__global__ void updates_kernel(const float* __restrict__ attn_in) {
    __shared__ float vs[32][256];
    __shared__ float as[KS][32];
    int b = blockIdx.y;
    int n0 = blockIdx.x * 512;
    int tid = threadIdx.x;
    int s = tid >> 5, lane = tid & 31, d8 = lane * 8;
    float acc[8];
#pragma unroll
    for (int i = 0; i < 8; i++) acc[i] = 0.f;
    for (int n1 = 0; n1 < 512; n1 += 32) {
        __syncthreads();
#pragma unroll
        for (int j = 0; j < 8; j++) {
            int id = tid + j * 256;
            int row = id >> 6, c4 = id & 63;
            *(float4*)&vs[row][c4*4] =
                *(const float4*)&d_kv[(size_t)(b * NN + n0 + n1 + row) * HKV + DD + c4 * 4];
        }
        as[s][lane] = attn_in[(size_t)(b * KS + s) * NN + n0 + n1 + lane];
        __syncthreads();
#pragma unroll
        for (int j = 0; j < 32; j++) {
            float a = as[s][j];
            float4 v0 = *(const float4*)&vs[j][d8];
            float4 v1 = *(const float4*)&vs[j][d8 + 4];
            acc[0] += a * v0.x; acc[1] += a * v0.y; acc[2] += a * v0.z; acc[3] += a * v0.w;
            acc[4] += a * v1.x; acc[5] += a * v1.y; acc[6] += a * v1.z; acc[7] += a * v1.w;
        }
    }
#pragma unroll
    for (int i = 0; i < 8; i++)
        atomicAdd(&d_updates[(b * KS + s) * DD + d8 + i], acc[i]);
}

/* ---------------- GRU cell: one block per slot row ---------------- */
__global__ void gru_kernel(const float* __restrict__ b_ih, const float* __restrict__ b_hh) {
    __shared__ float us[DD], ss[DD];
    int row = blockIdx.x, t = threadIdx.x;
    float inv = 1.f / (d_rowsum[row] + EPSN);
    us[t] = d_updates[row * DD + t] * inv;
    ss[t] = d_slots[row * DD + t];
    __syncthreads();
    float gir = 0.f, giz = 0.f, gin = 0.f, ghr = 0.f, ghz = 0.f, ghn = 0.f;
#pragma unroll 4
    for (int d = 0; d < DD; d++) {
        float u = us[d], sv = ss[d];
        const float* wi = &d_wihT[d * (3*DD)];
        const float* wh = &d_whhT[d * (3*DD)];
        gir += u * wi[t];        ghr += sv * wh[t];
        giz += u * wi[t + DD];   ghz += sv * wh[t + DD];
        gin += u * wi[t + 2*DD]; ghn += sv * wh[t + 2*DD];
    }
    gir += b_ih[t];        ghr += b_hh[t];
    giz += b_ih[t + DD];   ghz += b_hh[t + DD];
    gin += b_ih[t + 2*DD]; ghn += b_hh[t + 2*DD];
    float r = sigf(gir + ghr);
    float z = sigf(giz + ghz);
    float n = tanhf(gin + r * ghn);
    d_h[row * DD + t] = (1.f - z) * n + z * ss[t];
}

/* ---------------- MLP (LN -> W1,relu -> W2) + residual ---------------- */
__global__ void mlp_kernel(const float* __restrict__ g_m, const float* __restrict__ b_m,
                           const float* __restrict__ b1, const float* __restrict__ b2) {
    __shared__ float lnh[DD], m1[DD];
    __shared__ float ws[8], wq[8];
    int row = blockIdx.x, t = threadIdx.x;
    float h = d_h[row * DD + t];
    float s = h, q2 = h * h;
#pragma unroll
    for (int o = 16; o; o >>= 1) {
        s  += __shfl_xor_sync(0xffffffffu, s, o);
        q2 += __shfl_xor_sync(0xffffffffu, q2, o);
    }
    if ((t & 31) == 0) { ws[t >> 5] = s; wq[t >> 5] = q2; }
    __syncthreads();
    float S = 0.f, Q = 0.f;
#pragma unroll
    for (int i = 0; i < 8; i++) { S += ws[i]; Q += wq[i]; }
    float m = S * (1.f/DD);
    float rst = rsqrtf(Q * (1.f/DD) - m * m + 1e-5f);
    lnh[t] = (h - m) * rst * g_m[t] + b_m[t];
    __syncthreads();
    float a1 = 0.f;
#pragma unroll 8
    for (int d = 0; d < DD; d++) a1 += lnh[d] * d_w1T[d * DD + t];
    m1[t] = fmaxf(a1 + b1[t], 0.f);
    __syncthreads();
    float a2 = 0.f;
#pragma unroll 8
    for (int d = 0; d < DD; d++) a2 += m1[d] * d_w2T[d * DD + t];
    d_slots[row * DD + t] = h + a2 + b2[t];
}

/* ---------------- final blend ---------------- */
__global__ void final_out(const float* __restrict__ prev, float* __restrict__ out) {
    int row = blockIdx.x, t = threadIdx.x;
    float mask = sigf(d_rowsum[row] * (1.f / NN));
    out[row * DD + t] = d_slots[row * DD + t] * mask + prev[row * DD + t] * (1.f - mask);
}

/* ------------------------------ launch ------------------------------ */
extern "C" void kernel_launch(void* const* d_in, const int* in_sizes, int n_in,
                              void* d_out, int out_size) {
    const float* features = (const float*)d_in[0];
    const float* prev     = (const float*)d_in[1];
    const float* g_in     = (const float*)d_in[2];
    const float* b_in     = (const float*)d_in[3];
    const float* g_s      = (const float*)d_in[4];
    const float* b_s      = (const float*)d_in[5];
    const float* g_m      = (const float*)d_in[6];
    const float* b_m      = (const float*)d_in[7];
    const float* Wq       = (const float*)d_in[8];
    const float* Wk       = (const float*)d_in[9];
    const float* Wv       = (const float*)d_in[10];
    const float* W_ih     = (const float*)d_in[11];
    const float* W_hh     = (const float*)d_in[12];
    const float* b_ih     = (const float*)d_in[13];
    const float* b_hh     = (const float*)d_in[14];
    const float* W1       = (const float*)d_in[15];
    const float* b1       = (const float*)d_in[16];
    const float* W2       = (const float*)d_in[17];
    const float* b2       = (const float*)d_in[18];
    float* out = (float*)d_out;

    float* attn_scratch = nullptr;
    cudaGetSymbolAddress((void**)&attn_scratch, d_attn);
    /* Output layout: [0, SROWS*DD) = slots_out, [SROWS*DD, +SROWS*NN) = attn_final */
    float* attn_final = (out_size >= SROWS*DD + SROWS*NN) ? out + SROWS*DD : attn_scratch;

    /* prep — GEMM at my launch index 3 (harness seems to add ~2 launches;
     * ncu -s 5 -c 1 should then land on the GEMM) */
    copy_slots<<<SROWS*DD/256, 256>>>(prev);                       /* 0 */
    prep_wsplit<<<HKV, FF>>>(Wk, Wv, g_in);                        /* 1 */
    prep_c<<<HKV, 256>>>(Wk, Wv, g_in, b_in);                      /* 2 */
    {
        dim3 grid(HKV/128, NROWS/128);                             /* 3 */
        gemm_kv_mma<<<grid, 256>>>(features);
    }
    transpose_sel<<<(DD*DD+255)/256, 256>>>(Wq, DD, DD, 0);
    transpose_sel<<<(3*DD*DD+255)/256, 256>>>(W_ih, 3*DD, DD, 1);
    transpose_sel<<<(3*DD*DD+255)/256, 256>>>(W_hh, 3*DD, DD, 2);
    transpose_sel<<<(DD*DD+255)/256, 256>>>(W1, DD, DD, 3);
    transpose_sel<<<(DD*DD+255)/256, 256>>>(W2, DD, DD, 4);

    /* 3 slot-attention iterations */
    for (int it = 0; it < 3; it++) {
        slots_q<<<SROWS, DD>>>(g_s, b_s);
        zero_urs<<<SROWS*DD/256, 256>>>();
        {
            dim3 g(NN/512, BB);
            attn_kernel<<<g, 128>>>(attn_scratch);
            updates_kernel<<<g, 256>>>(attn_scratch);
        }
        gru_kernel<<<SROWS, DD>>>(b_ih, b_hh);
        mlp_kernel<<<SROWS, DD>>>(g_m, b_m, b1, b2);
    }

    /* final attention + confidence blend */
    slots_q<<<SROWS, DD>>>(g_s, b_s);
    zero_urs<<<SROWS*DD/256, 256>>>();
    {
        dim3 g(NN/512, BB);
        attn_kernel<<<g, 128>>>(attn_final);
    }
    final_out<<<SROWS, DD>>>(prev, out);
}

// round 13
// speedup vs baseline: 1.8682x; 1.2638x over previous
#include <cuda_runtime.h>
#include <cuda_bf16.h>
#include <cuda_fp16.h>
#include <math.h>
#include <stdint.h>

#define BB 32
#define NN 4096
#define FF 768
#define DD 256
#define KS 8
#define HKV 512
#define NROWS (BB*NN)
#define SROWS (BB*KS)
#define EPSN 1e-8f
#define QSCALE 0.0625f

/* ------------------ device scratch (static, no allocs) ------------------ */
static __device__ float d_kv[(size_t)NROWS*HKV];   /* k|v per row, 268MB */
static __device__ __half d_wphi[HKV*FF];
static __device__ __half d_wplo[HKV*FF];
static __device__ float d_c1[HKV];
static __device__ float d_c0[HKV];
static __device__ float d_wqT[DD*DD];
static __device__ float d_wihT[DD*3*DD];
static __device__ float d_whhT[DD*3*DD];
static __device__ float d_w1T[DD*DD];
static __device__ float d_w2T[DD*DD];
static __device__ float d_q[SROWS*DD];
static __device__ float d_attn[(size_t)SROWS*NN];
static __device__ float d_rowsum[SROWS];
static __device__ float d_updates[SROWS*DD];
static __device__ float d_h[SROWS*DD];
static __device__ float d_slots[SROWS*DD];

__device__ __forceinline__ float sigf(float x) { return 1.f / (1.f + __expf(-x)); }

__device__ __forceinline__ uint32_t smem_u32(const void* p) {
    uint32_t a;
    asm("{ .reg .u64 t; cvta.to.shared.u64 t, %1; cvt.u32.u64 %0, t; }" : "=r"(a) : "l"(p));
    return a;
}
__device__ __forceinline__ void ldm_x4(uint32_t* r, uint32_t addr) {
    asm volatile("ldmatrix.sync.aligned.m8n8.x4.shared.b16 {%0,%1,%2,%3}, [%4];"
        : "=r"(r[0]), "=r"(r[1]), "=r"(r[2]), "=r"(r[3]) : "r"(addr));
}
__device__ __forceinline__ void mma_f16(float* d, const uint32_t* a,
                                        uint32_t b0, uint32_t b1) {
    asm volatile("mma.sync.aligned.m16n8k16.row.col.f32.f16.f16.f32 "
        "{%0,%1,%2,%3}, {%4,%5,%6,%7}, {%8,%9}, {%0,%1,%2,%3};"
        : "+f"(d[0]), "+f"(d[1]), "+f"(d[2]), "+f"(d[3])
        : "r"(a[0]), "r"(a[1]), "r"(a[2]), "r"(a[3]), "r"(b0), "r"(b1));
}
__device__ __forceinline__ uint32_t pkh2(__half a, __half b) {
    return (uint32_t)__half_as_ushort(a) | ((uint32_t)__half_as_ushort(b) << 16);
}

/* ------------------------------ prep ------------------------------ */
__global__ void copy_slots(const float* __restrict__ prev) {
    int i = blockIdx.x * blockDim.x + threadIdx.x;
    d_slots[i] = prev[i];
}

/* Wp[h][f] = g_in[f] * W[h][f], split to fp16 hi/lo */
__global__ void prep_wsplit(const float* __restrict__ Wk, const float* __restrict__ Wv,
                            const float* __restrict__ g_in) {
    int h = blockIdx.x, f = threadIdx.x;
    float w = g_in[f] * ((h < DD) ? Wk[h*FF + f] : Wv[(h-DD)*FF + f]);
    __half hi = __float2half_rn(w);
    float lo = w - __half2float(hi);
    d_wphi[h*FF + f] = hi;
    d_wplo[h*FF + f] = __float2half_rn(lo);
}

__global__ void prep_c(const float* __restrict__ Wk, const float* __restrict__ Wv,
                       const float* __restrict__ g_in, const float* __restrict__ b_in) {
    __shared__ float r1[8], r0s[8];
    int h = blockIdx.x, t = threadIdx.x;
    const float* w = (h < DD) ? &Wk[h*FF] : &Wv[(h-DD)*FF];
    float s1 = 0.f, s0 = 0.f;
    for (int f = t; f < FF; f += 256) {
        float wv = w[f];
        s1 += g_in[f] * wv;
        s0 += b_in[f] * wv;
    }
#pragma unroll
    for (int o = 16; o; o >>= 1) {
        s1 += __shfl_xor_sync(0xffffffffu, s1, o);
        s0 += __shfl_xor_sync(0xffffffffu, s0, o);
    }
    if ((t & 31) == 0) { r1[t >> 5] = s1; r0s[t >> 5] = s0; }
    __syncthreads();
    if (t == 0) {
        float a = 0.f, b = 0.f;
#pragma unroll
        for (int i = 0; i < 8; i++) { a += r1[i]; b += r0s[i]; }
        d_c1[h] = a; d_c0[h] = b;
    }
}

__global__ void transpose_sel(const float* __restrict__ src, int R, int C, int which) {
    float* dst = (which == 0) ? d_wqT : (which == 1) ? d_wihT :
                 (which == 2) ? d_whhT : (which == 3) ? d_w1T : d_w2T;
    int idx = blockIdx.x * blockDim.x + threadIdx.x;
    if (idx < R * C) {
        int r = idx / C, c = idx - r * C;
        dst[c * R + r] = src[idx];
    }
}

/* ------- fused LN + KV GEMM via mma.sync (fp16, B hi/lo split) -------
 * Tile 128x128, BK=32, 8 warps (4M x 2N), warp tile 32x64.
 * B fragments via ldmatrix.x4 (was 64 scalar LDS/warp/chunk);
 * __launch_bounds__(256,2) for 2 CTAs/SM. */
#define ASTR 40   /* padded fp16 row stride for 32-col tiles */
__launch_bounds__(256, 2)
__global__ void gemm_kv_mma(const float* __restrict__ X) {
    __shared__ __half As[128*ASTR];
    __shared__ __half Bh[128*ASTR], Bl[128*ASTR];
    __shared__ float m_s[128], r_s[128], c1s[128], c0s[128];

    int tid = threadIdx.x;
    int wid = tid >> 5, lane = tid & 31;
    int c0b = blockIdx.x * 128;
    int r0  = blockIdx.y * 128;

    if (tid < 128) { c1s[tid] = d_c1[c0b + tid]; c0s[tid] = d_c0[c0b + tid]; }

    int arow = tid >> 1, aq = tid & 1;   /* A: row, 16-elem half */
    float ps = 0.f, pq = 0.f;

    int wm = wid >> 1, wn = wid & 1;
    int m_off = wm * 32, n_off = wn * 64;

    float acc[2][8][4];
#pragma unroll
    for (int mt = 0; mt < 2; mt++)
#pragma unroll
        for (int nt = 0; nt < 8; nt++)
#pragma unroll
            for (int j = 0; j < 4; j++) acc[mt][nt][j] = 0.f;

    /* ldmatrix lane->address mapping (A, 16x16 tiles) */
    uint32_t a_base = smem_u32(As) +
        (uint32_t)(((m_off + (lane & 15)) * ASTR + (lane >> 4) * 8) * 2);
    /* ldmatrix lane->address mapping (B): x4 covers nt pair p:
     * group=lane>>3: 0:(nt=2p,k0-7) 1:(nt=2p,k8-15) 2:(nt=2p+1,k0-7) 3:(nt=2p+1,k8-15) */
    int bg = lane >> 3, brow = lane & 7;
    int b_n = n_off + ((bg >> 1) << 3) + brow;
    int b_k = (bg & 1) << 3;
    uint32_t b_h_base = smem_u32(Bh) + (uint32_t)((b_n * ASTR + b_k) * 2);
    uint32_t b_l_base = smem_u32(Bl) + (uint32_t)((b_n * ASTR + b_k) * 2);

    for (int ch = 0; ch < 24; ch++) {
        int k0 = ch * 32;
        __syncthreads();
        /* A tile: coalesced f32 load + stats + fp16 convert to smem */
        {
            const float* xp = &X[(size_t)(r0 + arow) * FF + k0 + aq * 16];
#pragma unroll
            for (int i = 0; i < 4; i++) {
                float4 a = *(const float4*)&xp[i * 4];
                ps += a.x + a.y + a.z + a.w;
                pq += a.x*a.x + a.y*a.y + a.z*a.z + a.w*a.w;
                uint2 u;
                u.x = pkh2(__float2half_rn(a.x), __float2half_rn(a.y));
                u.y = pkh2(__float2half_rn(a.z), __float2half_rn(a.w));
                *(uint2*)&As[arow * ASTR + aq * 16 + i * 4] = u;
            }
        }
        /* B tile: copy precomputed fp16 hi/lo — 16 halves = 2x uint4 */
        {
            size_t g = (size_t)(c0b + arow) * FF + k0 + aq * 16;
            int o = arow * ASTR + aq * 16;
            *(uint4*)&Bh[o]     = *(const uint4*)&d_wphi[g];
            *(uint4*)&Bh[o + 8] = *(const uint4*)&d_wphi[g + 8];
            *(uint4*)&Bl[o]     = *(const uint4*)&d_wplo[g];
            *(uint4*)&Bl[o + 8] = *(const uint4*)&d_wplo[g + 8];
        }
        __syncthreads();

#pragma unroll
        for (int s = 0; s < 2; s++) {
            uint32_t af[2][4];
#pragma unroll
            for (int mt = 0; mt < 2; mt++)
                ldm_x4(af[mt], a_base + (uint32_t)(mt * 16 * ASTR * 2 + s * 32));

            uint32_t bhf[4][4], blf[4][4];
#pragma unroll
            for (int p = 0; p < 4; p++) {
                uint32_t off = (uint32_t)((p * 16 * ASTR + s * 16) * 2);
                ldm_x4(bhf[p], b_h_base + off);
                ldm_x4(blf[p], b_l_base + off);
            }
#pragma unroll
            for (int nt = 0; nt < 8; nt++) {
                int p = nt >> 1, q = (nt & 1) * 2;
#pragma unroll
                for (int mt = 0; mt < 2; mt++) {
                    mma_f16(acc[mt][nt], af[mt], bhf[p][q], bhf[p][q + 1]);
                    mma_f16(acc[mt][nt], af[mt], blf[p][q], blf[p][q + 1]);
                }
            }
        }
    }

    /* LN stats: pair (tid, tid^1) shares row arow */
    ps += __shfl_xor_sync(0xffffffffu, ps, 1);
    pq += __shfl_xor_sync(0xffffffffu, pq, 1);
    if (aq == 0) {
        float m = ps * (1.f / FF);
        m_s[arow] = m;
        r_s[arow] = rsqrtf(pq * (1.f / FF) - m * m + 1e-5f);
    }
    __syncthreads();

    /* epilogue: apply LN fold, write fp32 */
    int g = lane >> 2, c2 = (lane & 3) * 2;
#pragma unroll
    for (int mt = 0; mt < 2; mt++) {
#pragma unroll
        for (int rr = 0; rr < 2; rr++) {
            int row = m_off + mt * 16 + g + rr * 8;
            float m = m_s[row], rs = r_s[row];
            float* dst = &d_kv[(size_t)(r0 + row) * HKV + c0b];
#pragma unroll
            for (int nt = 0; nt < 8; nt++) {
                int col = n_off + nt * 8 + c2;
                float2 o;
                o.x = rs * (acc[mt][nt][rr*2+0] - m * c1s[col])     + c0s[col];
                o.y = rs * (acc[mt][nt][rr*2+1] - m * c1s[col + 1]) + c0s[col + 1];
                *(float2*)&dst[col] = o;
            }
        }
    }
}

/* ---------------- slots LN + q projection (q *= SCALE) ---------------- */
__global__ void slots_q(const float* __restrict__ g_s, const float* __restrict__ b_s) {
    __shared__ float lnr[DD];
    __shared__ float ws[8], wq[8];
    int row = blockIdx.x, t = threadIdx.x;
    float x = d_slots[row * DD + t];
    float s = x, q2 = x * x;
#pragma unroll
    for (int o = 16; o; o >>= 1) {
        s  += __shfl_xor_sync(0xffffffffu, s, o);
        q2 += __shfl_xor_sync(0xffffffffu, q2, o);
    }
    if ((t & 31) == 0) { ws[t >> 5] = s; wq[t >> 5] = q2; }
    __syncthreads();
    float S = 0.f, Q = 0.f;
#pragma unroll
    for (int i = 0; i < 8; i++) { S += ws[i]; Q += wq[i]; }
    float m = S * (1.f/DD);
    float rst = rsqrtf(Q * (1.f/DD) - m * m + 1e-5f);
    lnr[t] = (x - m) * rst * g_s[t] + b_s[t];
    __syncthreads();
    float acc = 0.f;
#pragma unroll 8
    for (int d = 0; d < DD; d++) acc += lnr[d] * d_wqT[d * DD + t];
    d_q[row * DD + t] = acc * QSCALE;
}

__global__ void zero_urs() {
    int i = blockIdx.x * blockDim.x + threadIdx.x;
    if (i < SROWS) d_rowsum[i] = 0.f;
    d_updates[i] = 0.f;
}

/* -------- logits + softmax over K + rowsum; 128 thr, 512 n/block -------- */
__launch_bounds__(128)
__global__ void attn_kernel(float* __restrict__ attn_out) {
    __shared__ float qs[KS * DD];
    __shared__ float ks[16][516];
    int b = blockIdx.y;
    int n0 = blockIdx.x * 512;
    int tid = threadIdx.x;

    for (int i = tid; i < KS * DD; i += 128) qs[i] = d_q[b * KS * DD + i];

    float acc[KS][4];
#pragma unroll
    for (int s = 0; s < KS; s++)
#pragma unroll
        for (int j = 0; j < 4; j++) acc[s][j] = 0.f;

    for (int h0 = 0; h0 < DD; h0 += 16) {
        __syncthreads();
#pragma unroll
        for (int j = 0; j < 16; j++) {
            int id = tid + j * 128;
            int row = id >> 2, c4 = id & 3;
            float4 v = *(const float4*)&d_kv[(size_t)(b * NN + n0 + row) * HKV + h0 + c4 * 4];
            ks[c4*4+0][row] = v.x; ks[c4*4+1][row] = v.y;
            ks[c4*4+2][row] = v.z; ks[c4*4+3][row] = v.w;
        }
        __syncthreads();
#pragma unroll
        for (int hh = 0; hh < 16; hh++) {
            float4 kv = *(const float4*)&ks[hh][tid * 4];
#pragma unroll
            for (int s = 0; s < KS; s++) {
                float q = qs[s * DD + h0 + hh];
                acc[s][0] += q * kv.x; acc[s][1] += q * kv.y;
                acc[s][2] += q * kv.z; acc[s][3] += q * kv.w;
            }
        }
    }
    int nb = n0 + tid * 4;
    float rsum[KS];
#pragma unroll
    for (int s = 0; s < KS; s++) rsum[s] = 0.f;
#pragma unroll
    for (int j = 0; j < 4; j++) {
        float mx = acc[0][j];
#pragma unroll
        for (int s = 1; s < KS; s++) mx = fmaxf(mx, acc[s][j]);
        float den = 0.f;
#pragma unroll
        for (int s = 0; s < KS; s++) { acc[s][j] = __expf(acc[s][j] - mx); den += acc[s][j]; }
        float inv = 1.f / den;
#pragma unroll
        for (int s = 0; s < KS; s++) { acc[s][j] *= inv; rsum[s] += acc[s][j]; }
    }
#pragma unroll
    for (int s = 0; s < KS; s++) {
        float4 o = make_float4(acc[s][0], acc[s][1], acc[s][2], acc[s][3]);
        *(float4*)&attn_out[(size_t)(b * KS + s) * NN + nb] = o;
    }
#pragma unroll
    for (int s = 0; s < KS; s++) {
        float v = rsum[s];
#pragma unroll
        for (int o = 16; o; o >>= 1) v += __shfl_xor_sync(0xffffffffu, v, o);
        if ((tid & 31) == 0) atomicAdd(&d_rowsum[b * KS + s], v);
    }
}

/* ---------------- updates += attn @ v (unnormalized) ---------------- */
__launch_bounds__(256)
__global__ void updates_kernel(const float* __restrict__ attn_in) {
    __shared__ float vs[32][256];
    __shared__ float as[KS][32];
    int b = blockIdx.y;
    int n0 = blockIdx.x * 512;
    int tid = threadIdx.x;
    int s = tid >> 5, lane = tid & 31, d8 = lane * 8;
    float acc[8];
#pragma unroll
    for (int i = 0; i < 8; i++) acc[i] = 0.f;
    for (int n1 = 0; n1 < 512; n1 += 32) {
        __syncthreads();
#pragma unroll
        for (int j = 0; j < 8; j++) {
            int id = tid + j * 256;
            int row = id >> 6, c4 = id & 63;
            *(float4*)&vs[row][c4*4] =
                *(const float4*)&d_kv[(size_t)(b * NN + n0 + n1 + row) * HKV + DD + c4 * 4];
        }
        as[s][lane] = attn_in[(size_t)(b * KS + s) * NN + n0 + n1 + lane];
        __syncthreads();
#pragma unroll
        for (int j = 0; j < 32; j++) {
            float a = as[s][j];
            float4 v0 = *(const float4*)&vs[j][d8];
            float4 v1 = *(const float4*)&vs[j][d8 + 4];
            acc[0] += a * v0.x; acc[1] += a * v0.y; acc[2] += a * v0.z; acc[3] += a * v0.w;
            acc[4] += a * v1.x; acc[5] += a * v1.y; acc[6] += a * v1.z; acc[7] += a * v1.w;
        }
    }
#pragma unroll
    for (int i = 0; i < 8; i++)
        atomicAdd(&d_updates[(b * KS + s) * DD + d8 + i], acc[i]);
}

/* ---------------- GRU cell: one block per slot row ---------------- */
__global__ void gru_kernel(const float* __restrict__ b_ih, const float* __restrict__ b_hh) {
    __shared__ float us[DD], ss[DD];
    int row = blockIdx.x, t = threadIdx.x;
    float inv = 1.f / (d_rowsum[row] + EPSN);
    us[t] = d_updates[row * DD + t] * inv;
    ss[t] = d_slots[row * DD + t];
    __syncthreads();
    float gir = 0.f, giz = 0.f, gin = 0.f, ghr = 0.f, ghz = 0.f, ghn = 0.f;
#pragma unroll 4
    for (int d = 0; d < DD; d++) {
        float u = us[d], sv = ss[d];
        const float* wi = &d_wihT[d * (3*DD)];
        const float* wh = &d_whhT[d * (3*DD)];
        gir += u * wi[t];        ghr += sv * wh[t];
        giz += u * wi[t + DD];   ghz += sv * wh[t + DD];
        gin += u * wi[t + 2*DD]; ghn += sv * wh[t + 2*DD];
    }
    gir += b_ih[t];        ghr += b_hh[t];
    giz += b_ih[t + DD];   ghz += b_hh[t + DD];
    gin += b_ih[t + 2*DD]; ghn += b_hh[t + 2*DD];
    float r = sigf(gir + ghr);
    float z = sigf(giz + ghz);
    float n = tanhf(gin + r * ghn);
    d_h[row * DD + t] = (1.f - z) * n + z * ss[t];
}

/* ---------------- MLP (LN -> W1,relu -> W2) + residual ---------------- */
__global__ void mlp_kernel(const float* __restrict__ g_m, const float* __restrict__ b_m,
                           const float* __restrict__ b1, const float* __restrict__ b2) {
    __shared__ float lnh[DD], m1[DD];
    __shared__ float ws[8], wq[8];
    int row = blockIdx.x, t = threadIdx.x;
    float h = d_h[row * DD + t];
    float s = h, q2 = h * h;
#pragma unroll
    for (int o = 16; o; o >>= 1) {
        s  += __shfl_xor_sync(0xffffffffu, s, o);
        q2 += __shfl_xor_sync(0xffffffffu, q2, o);
    }
    if ((t & 31) == 0) { ws[t >> 5] = s; wq[t >> 5] = q2; }
    __syncthreads();
    float S = 0.f, Q = 0.f;
#pragma unroll
    for (int i = 0; i < 8; i++) { S += ws[i]; Q += wq[i]; }
    float m = S * (1.f/DD);
    float rst = rsqrtf(Q * (1.f/DD) - m * m + 1e-5f);
    lnh[t] = (h - m) * rst * g_m[t] + b_m[t];
    __syncthreads();
    float a1 = 0.f;
#pragma unroll 8
    for (int d = 0; d < DD; d++) a1 += lnh[d] * d_w1T[d * DD + t];
    m1[t] = fmaxf(a1 + b1[t], 0.f);
    __syncthreads();
    float a2 = 0.f;
#pragma unroll 8
    for (int d = 0; d < DD; d++) a2 += m1[d] * d_w2T[d * DD + t];
    d_slots[row * DD + t] = h + a2 + b2[t];
}

/* ---------------- final blend ---------------- */
__global__ void final_out(const float* __restrict__ prev, float* __restrict__ out) {
    int row = blockIdx.x, t = threadIdx.x;
    float mask = sigf(d_rowsum[row] * (1.f / NN));
    out[row * DD + t] = d_slots[row * DD + t] * mask + prev[row * DD + t] * (1.f - mask);
}

/* ------------------------------ launch ------------------------------ */
extern "C" void kernel_launch(void* const* d_in, const int* in_sizes, int n_in,
                              void* d_out, int out_size) {
    const float* features = (const float*)d_in[0];
    const float* prev     = (const float*)d_in[1];
    const float* g_in     = (const float*)d_in[2];
    const float* b_in     = (const float*)d_in[3];
    const float* g_s      = (const float*)d_in[4];
    const float* b_s      = (const float*)d_in[5];
    const float* g_m      = (const float*)d_in[6];
    const float* b_m      = (const float*)d_in[7];
    const float* Wq       = (const float*)d_in[8];
    const float* Wk       = (const float*)d_in[9];
    const float* Wv       = (const float*)d_in[10];
    const float* W_ih     = (const float*)d_in[11];
    const float* W_hh     = (const float*)d_in[12];
    const float* b_ih     = (const float*)d_in[13];
    const float* b_hh     = (const float*)d_in[14];
    const float* W1       = (const float*)d_in[15];
    const float* b1       = (const float*)d_in[16];
    const float* W2       = (const float*)d_in[17];
    const float* b2       = (const float*)d_in[18];
    float* out = (float*)d_out;

    float* attn_scratch = nullptr;
    cudaGetSymbolAddress((void**)&attn_scratch, d_attn);
    /* Output layout: [0, SROWS*DD) = slots_out, [SROWS*DD, +SROWS*NN) = attn_final */
    float* attn_final = (out_size >= SROWS*DD + SROWS*NN) ? out + SROWS*DD : attn_scratch;

    copy_slots<<<SROWS*DD/256, 256>>>(prev);                       /* 0 */
    prep_wsplit<<<HKV, FF>>>(Wk, Wv, g_in);                        /* 1 */
    prep_c<<<HKV, 256>>>(Wk, Wv, g_in, b_in);                      /* 2 */
    {
        dim3 grid(HKV/128, NROWS/128);                             /* 3 */
        gemm_kv_mma<<<grid, 256>>>(features);
    }
    transpose_sel<<<(DD*DD+255)/256, 256>>>(Wq, DD, DD, 0);
    transpose_sel<<<(3*DD*DD+255)/256, 256>>>(W_ih, 3*DD, DD, 1);
    transpose_sel<<<(3*DD*DD+255)/256, 256>>>(W_hh, 3*DD, DD, 2);
    transpose_sel<<<(DD*DD+255)/256, 256>>>(W1, DD, DD, 3);
    transpose_sel<<<(DD*DD+255)/256, 256>>>(W2, DD, DD, 4);

    /* 3 slot-attention iterations */
    for (int it = 0; it < 3; it++) {
        slots_q<<<SROWS, DD>>>(g_s, b_s);
        zero_urs<<<SROWS*DD/256, 256>>>();
        {
            dim3 g(NN/512, BB);
            attn_kernel<<<g, 128>>>(attn_scratch);
            updates_kernel<<<g, 256>>>(attn_scratch);
        }
        gru_kernel<<<SROWS, DD>>>(b_ih, b_hh);
        mlp_kernel<<<SROWS, DD>>>(g_m, b_m, b1, b2);
    }

    /* final attention + confidence blend */
    slots_q<<<SROWS, DD>>>(g_s, b_s);
    zero_urs<<<SROWS*DD/256, 256>>>();
    {
        dim3 g(NN/512, BB);
        attn_kernel<<<g, 128>>>(attn_final);
    }
    final_out<<<SROWS, DD>>>(prev, out);
}